// round 14
// baseline (speedup 1.0000x reference)
#include <cuda_runtime.h>
#include <cuda_bf16.h>
#include <stdint.h>
#include <math.h>

#define NN 1024
#define DIM 512
#define HH 8
#define DD 64
#define CC 64
#define SCALE 0.125f
#define NEGF -1e30f

// ---------------- scratch ----------------
__device__ float g_xr [NN*DIM];
__device__ __nv_bfloat16 g_xnh[NN*DIM], g_xnl[NN*DIM];
__device__ float g_gate[NN*24];
__device__ float g_q  [HH*NN*DD];
__device__ float g_k  [HH*NN*DD];
__device__ float g_v  [HH*NN*DD];
__device__ float g_ckf[HH*65*DD];
__device__ float g_cvf[HH*65*DD];
__device__ float g_cout[HH*NN*DD];
__device__ float g_fout[HH*NN*DD];
__device__ float g_sout[HH*NN*DD];
__device__ __nv_bfloat16 g_ohi[NN*DIM], g_olo[NN*DIM];
__device__ float g_x2 [NN*DIM];
__device__ __nv_bfloat16 g_hhi[NN*2048], g_hlo[NN*2048];
// transposed bf16 hi/lo weights: [Nout][K]
__device__ __nv_bfloat16 g_wqkvTh[1600*512], g_wqkvTl[1600*512];
__device__ __nv_bfloat16 g_woTh[512*512],    g_woTl[512*512];
__device__ __nv_bfloat16 g_w1Th[2048*512],   g_w1Tl[2048*512];
__device__ __nv_bfloat16 g_w2Th[512*2048],   g_w2Tl[512*2048];

// ---------------- helpers ----------------
__device__ __forceinline__ uint32_t smem_u32(const void* p) {
    uint32_t a;
    asm("{ .reg .u64 t; cvta.to.shared.u64 t, %1; cvt.u32.u64 %0, t; }" : "=r"(a) : "l"(p));
    return a;
}
__device__ __forceinline__ uint32_t swz(uint32_t off) { return off ^ ((off >> 3) & 0x70); }

#define LDSM_X4(r, addr) \
    asm volatile("ldmatrix.sync.aligned.m8n8.x4.shared.b16 {%0,%1,%2,%3}, [%4];" \
        : "=r"((r)[0]),"=r"((r)[1]),"=r"((r)[2]),"=r"((r)[3]) : "r"(addr))
#define LDSM_X2(r, addr) \
    asm volatile("ldmatrix.sync.aligned.m8n8.x2.shared.b16 {%0,%1}, [%2];" \
        : "=r"((r)[0]),"=r"((r)[1]) : "r"(addr))
#define CP16(dst, src) \
    asm volatile("cp.async.cg.shared.global [%0], [%1], 16;" :: "r"(dst), "l"(src))
#define CP_COMMIT() asm volatile("cp.async.commit_group;" ::: "memory")
#define CP_WAIT(n)  asm volatile("cp.async.wait_group %0;" :: "n"(n) : "memory")

__device__ __forceinline__ void mma16816(float* d, const uint32_t* a, const uint32_t* b) {
    asm volatile("mma.sync.aligned.m16n8k16.row.col.f32.bf16.bf16.f32 "
        "{%0,%1,%2,%3}, {%4,%5,%6,%7}, {%8,%9}, {%0,%1,%2,%3};"
        : "+f"(d[0]),"+f"(d[1]),"+f"(d[2]),"+f"(d[3])
        : "r"(a[0]),"r"(a[1]),"r"(a[2]),"r"(a[3]), "r"(b[0]),"r"(b[1]));
}
__device__ __forceinline__ void split_bf(float x, __nv_bfloat16& h, __nv_bfloat16& l) {
    h = __float2bfloat16(x);
    l = __float2bfloat16(x - __bfloat162float(h));
}

// ---------------- ONE fused weight transpose+split kernel ----------------
__global__ void k_convAll(const float* __restrict__ Wq, const float* __restrict__ Wk,
                          const float* __restrict__ Wv, const float* __restrict__ Wo,
                          const float* __restrict__ W1, const float* __restrict__ W2,
                          const float* __restrict__ Wg) {
    __shared__ __nv_bfloat16 th[32][33], tl[32][33];
    int t = blockIdx.x;
    const float* src; __nv_bfloat16 *dh, *dl;
    int K, N, rowOff; bool wg = false;
    if (t < 1024) {
        int s = t >> 8; t &= 255; K = 512; N = 512;
        if (s == 0)      { src = Wq; dh = g_wqkvTh; dl = g_wqkvTl; rowOff = 0; }
        else if (s == 1) { src = Wk; dh = g_wqkvTh; dl = g_wqkvTl; rowOff = 512; }
        else if (s == 2) { src = Wv; dh = g_wqkvTh; dl = g_wqkvTl; rowOff = 1024; }
        else             { src = Wo; dh = g_woTh;   dl = g_woTl;   rowOff = 0; }
    } else if (t < 2048) { t -= 1024; src = W1; dh = g_w1Th; dl = g_w1Tl; K = 512;  N = 2048; rowOff = 0; }
    else if (t < 3072)   { t -= 2048; src = W2; dh = g_w2Th; dl = g_w2Tl; K = 2048; N = 512;  rowOff = 0; }
    else { t -= 3072; src = Wg; dh = g_wqkvTh; dl = g_wqkvTl; K = 512; N = 64; rowOff = 1536; wg = true; }
    int tilesN = N >> 5;
    int tN = (t % tilesN)*32, tK = (t / tilesN)*32;
    int tx = threadIdx.x, ty = threadIdx.y;
#pragma unroll
    for (int r = 0; r < 4; r++) {
        int k = tK + ty + r*8, n = tN + tx;
        float v;
        if (wg) v = (n < 24) ? src[(size_t)k*24 + n] : 0.f;
        else    v = src[(size_t)k*N + n];
        __nv_bfloat16 h, l; split_bf(v, h, l);
        th[ty + r*8][tx] = h; tl[ty + r*8][tx] = l;
    }
    __syncthreads();
#pragma unroll
    for (int r = 0; r < 4; r++) {
        int n = tN + ty + r*8, k = tK + tx;
        size_t o = (size_t)(rowOff + n)*K + k;
        dh[o] = th[tx][ty + r*8];
        dl[o] = tl[tx][ty + r*8];
    }
}

// ---------------- HMMA GEMM with cp.async 2-stage pipeline ----------------
// MODE 1: Cf = acc + R.  MODE 2: Chi/Clo = split(relu(acc)^2).
// MODE 3 (QKV, TN=64): epilogue stages tile in smem, applies rope/transpose,
//         writes g_q/g_k/g_v/g_gate directly.
template<int TN, int MODE>
__global__ void __launch_bounds__(256, 2)
hm_gemm(const __nv_bfloat16* __restrict__ Ahi, const __nv_bfloat16* __restrict__ Alo,
        const __nv_bfloat16* __restrict__ Bhi, const __nv_bfloat16* __restrict__ Blo,
        const float* __restrict__ R, float* __restrict__ Cf,
        __nv_bfloat16* __restrict__ Chi, __nv_bfloat16* __restrict__ Clo,
        int K, int Nfull) {
    constexpr int NT = TN / 16;
    constexpr int STG = 32768 + 2*TN*128;
    extern __shared__ char dsm[];
    const uint32_t sb = smem_u32(dsm);
    int tid = threadIdx.x, wid = tid >> 5, lane = tid & 31;
    int wm = wid & 3, wn = wid >> 2;
    int rowBase = blockIdx.y*128, colBase = blockIdx.x*TN;

    float acc[2][NT][4];
#pragma unroll
    for (int mt = 0; mt < 2; mt++)
#pragma unroll
        for (int nt = 0; nt < NT; nt++)
#pragma unroll
            for (int r = 0; r < 4; r++) acc[mt][nt][r] = 0.f;

    auto issue = [&](int kc, int s) {
        uint32_t aH = sb + s*STG, aL = aH + 16384, bH = aH + 32768, bL = bH + TN*128;
        int rowL = tid >> 1, cb = (tid & 1)*4;
        const char* sAh = (const char*)(Ahi + ((size_t)(rowBase + rowL))*K + kc*64) + cb*16;
        const char* sAl = (const char*)(Alo + ((size_t)(rowBase + rowL))*K + kc*64) + cb*16;
#pragma unroll
        for (int j = 0; j < 4; j++) {
            uint32_t sw = swz((uint32_t)(rowL*128 + (cb + j)*16));
            CP16(aH + sw, sAh + j*16);
            CP16(aL + sw, sAl + j*16);
        }
#pragma unroll
        for (int it = 0; it < TN*8/256; it++) {
            int idx = tid + it*256;
            int n = idx >> 3, j = idx & 7;
            const char* sBh = (const char*)(Bhi + ((size_t)(colBase + n))*K + kc*64) + j*16;
            const char* sBl = (const char*)(Blo + ((size_t)(colBase + n))*K + kc*64) + j*16;
            uint32_t sw = swz((uint32_t)(n*128 + j*16));
            CP16(bH + sw, sBh);
            CP16(bL + sw, sBl);
        }
    };
    auto compute = [&](int s) {
        uint32_t A_H = sb + s*STG, A_L = A_H + 16384, B_H = A_H + 32768, B_L = B_H + TN*128;
#pragma unroll
        for (int ks = 0; ks < 4; ks++) {
            uint32_t ah[2][4], al[2][4], bh[NT][2], bl[NT][2];
#pragma unroll
            for (int mt = 0; mt < 2; mt++) {
                uint32_t off = swz((uint32_t)((wm*32 + mt*16 + (lane & 15))*128
                                              + ks*32 + (lane >> 4)*16));
                LDSM_X4(ah[mt], A_H + off);
                LDSM_X4(al[mt], A_L + off);
            }
#pragma unroll
            for (int nt = 0; nt < NT; nt++) {
                uint32_t off = swz((uint32_t)((wn*(TN/2) + nt*8 + (lane & 7))*128
                                              + ks*32 + ((lane >> 3) & 1)*16));
                LDSM_X2(bh[nt], B_H + off);
                LDSM_X2(bl[nt], B_L + off);
            }
#pragma unroll
            for (int mt = 0; mt < 2; mt++)
#pragma unroll
                for (int nt = 0; nt < NT; nt++) {
                    mma16816(acc[mt][nt], ah[mt], bh[nt]);
                    mma16816(acc[mt][nt], al[mt], bh[nt]);
                    mma16816(acc[mt][nt], ah[mt], bl[nt]);
                }
        }
    };

    int nCh = K >> 6;
    issue(0, 0); CP_COMMIT();
    for (int kc = 0; kc < nCh; kc++) {
        if (kc + 1 < nCh) { issue(kc + 1, (kc + 1) & 1); CP_COMMIT(); CP_WAIT(1); }
        else CP_WAIT(0);
        __syncthreads();
        compute(kc & 1);
        __syncthreads();
    }

    if (MODE == 3) {
        // stage tile in smem (fp32, padded rows), then rope/transpose/store
        float* ts = (float*)dsm;   // [128][66]
#pragma unroll
        for (int mt = 0; mt < 2; mt++)
#pragma unroll
            for (int nt = 0; nt < NT; nt++)
#pragma unroll
                for (int half = 0; half < 2; half++) {
                    int rl = wm*32 + mt*16 + (lane >> 2) + half*8;
                    int cl = wn*(TN/2) + nt*8 + (lane & 3)*2;
                    ts[rl*66 + cl]     = acc[mt][nt][half*2];
                    ts[rl*66 + cl + 1] = acc[mt][nt][half*2 + 1];
                }
        __syncthreads();
        if (colBase >= 1536) {
            // gates: cols 0..23 valid
            for (int idx = tid; idx < 128*24; idx += 256) {
                int r = idx / 24, c = idx - r*24;
                g_gate[(rowBase + r)*24 + c] = ts[r*66 + c];
            }
        } else {
            int h = (colBase >> 6) & 7;      // head within its q/k/v group
            int kind = colBase >> 9;         // 0=q, 1=k, 2=v
            if (kind == 2) {
                for (int idx = tid; idx < 8192; idx += 256) {
                    int r = idx >> 6, d = idx & 63;
                    g_v[(h*NN + rowBase + r)*64 + d] = ts[r*66 + d];
                }
            } else {
                float* dst = kind ? g_k : g_q;
                for (int idx = tid; idx < 4096; idx += 256) {
                    int r = idx >> 5, dp = idx & 31;
                    int n = rowBase + r;
                    float inv = expf(-(float)dp * (9.210340371976184f/32.f));
                    float ang = (float)n * inv;
                    float cs = cosf(ang), sn = sinf(ang);
                    float a = ts[r*66 + dp], b = ts[r*66 + dp + 32];
                    int o = (h*NN + n)*64;
                    dst[o + dp]      = a*cs - b*sn;
                    dst[o + dp + 32] = b*cs + a*sn;
                }
            }
        }
        return;
    }

#pragma unroll
    for (int mt = 0; mt < 2; mt++) {
#pragma unroll
        for (int nt = 0; nt < NT; nt++) {
#pragma unroll
            for (int half = 0; half < 2; half++) {
                int r = rowBase + wm*32 + mt*16 + (lane >> 2) + half*8;
#pragma unroll
                for (int q = 0; q < 2; q++) {
                    int c = colBase + wn*(TN/2) + nt*8 + (lane & 3)*2 + q;
                    float v = acc[mt][nt][half*2 + q];
                    size_t o = (size_t)r*Nfull + c;
                    if (MODE == 2) {
                        v = fmaxf(v, 0.f); v *= v;
                        __nv_bfloat16 h, l; split_bf(v, h, l);
                        Chi[o] = h; Clo[o] = l;
                    } else {
                        if (MODE == 1) v += R[o];
                        Cf[o] = v;
                    }
                }
            }
        }
    }
}

// ---------------- prelude ----------------
__global__ void k_prelude(const float* __restrict__ x, const float* __restrict__ x0,
                          const float* __restrict__ lam) {
    int n = blockIdx.x, tid = threadIdx.x;
    __shared__ float red[128];
    float l0 = lam[0], l1 = lam[1];
    float v[4]; float ss = 0.f;
#pragma unroll
    for (int r = 0; r < 4; r++) {
        int d = tid + r*128;
        float t = l0*x[n*DIM+d] + l1*x0[n*DIM+d];
        v[r] = t; g_xr[n*DIM+d] = t; ss += t*t;
    }
    red[tid] = ss; __syncthreads();
    for (int s = 64; s > 0; s >>= 1) { if (tid < s) red[tid] += red[tid+s]; __syncthreads(); }
    float rms = rsqrtf(red[0]*(1.f/512.f) + 1e-6f);
#pragma unroll
    for (int r = 0; r < 4; r++) {
        int d = tid + r*128; float t = v[r]*rms;
        __nv_bfloat16 h, l; split_bf(t, h, l);
        g_xnh[n*DIM+d] = h; g_xnl[n*DIM+d] = l;
    }
}

__global__ void k_rmsnorm2() {
    int n = blockIdx.x, tid = threadIdx.x;
    __shared__ float red[128];
    float v[4]; float ss = 0.f;
#pragma unroll
    for (int r = 0; r < 4; r++) { int d = tid + r*128; float t = g_x2[n*DIM+d]; v[r]=t; ss += t*t; }
    red[tid] = ss; __syncthreads();
    for (int s = 64; s > 0; s >>= 1) { if (tid < s) red[tid] += red[tid+s]; __syncthreads(); }
    float rms = rsqrtf(red[0]*(1.f/512.f) + 1e-6f);
#pragma unroll
    for (int r = 0; r < 4; r++) {
        int d = tid + r*128; float t = v[r]*rms;
        __nv_bfloat16 h, l; split_bf(t, h, l);
        g_xnh[n*DIM+d] = h; g_xnl[n*DIM+d] = l;
    }
}

// ---------------- compressed K/V: one block per c, all 8 heads ----------------
__global__ void __launch_bounds__(512) k_ckcv(
        const float* __restrict__ kpos, const float* __restrict__ vpos,
        const float* __restrict__ Wck, const float* __restrict__ bck,
        const float* __restrict__ Wcv, const float* __restrict__ bcv,
        const float* __restrict__ kmem, const float* __restrict__ vmem) {
    extern __shared__ float sm[];
    float* kbs = sm;
    float* vbs = sm + 8192;
    float* redk = sm + 16384;
    float* redv = sm + 20480;
    int c = blockIdx.x, tid = threadIdx.x;
    for (int idx = tid; idx < 8192; idx += 512) {
        int h = idx >> 10, e = idx & 1023, j = e >> 6, d = e & 63;
        kbs[idx] = g_k[(h*NN + c*16 + j)*64 + d] + kpos[idx];
        vbs[idx] = g_v[(h*NN + c*16 + j)*64 + d] + vpos[idx];
    }
    __syncthreads();
    int part = tid >> 6, d = tid & 63;
    float ak[8] = {}, av[8] = {};
    int e0 = part*128;
    for (int e = e0; e < e0 + 128; e++) {
        float wk = Wck[e*64 + d], wv = Wcv[e*64 + d];
#pragma unroll
        for (int h = 0; h < 8; h++) {
            ak[h] += kbs[h*1024 + e]*wk;
            av[h] += vbs[h*1024 + e]*wv;
        }
    }
#pragma unroll
    for (int h = 0; h < 8; h++) {
        redk[(part*8 + h)*64 + d] = ak[h];
        redv[(part*8 + h)*64 + d] = av[h];
    }
    __syncthreads();
    {
        int h = tid >> 6, dd = tid & 63;
        float sk = bck[dd], sv = bcv[dd];
#pragma unroll
        for (int p = 0; p < 8; p++) {
            sk += redk[(p*8 + h)*64 + dd];
            sv += redv[(p*8 + h)*64 + dd];
        }
        g_ckf[(h*65 + 1 + c)*64 + dd] = sk;
        g_cvf[(h*65 + 1 + c)*64 + dd] = sv;
        if (c == 0) {
            g_ckf[h*65*64 + dd] = kmem[h*64 + dd];
            g_cvf[h*65*64 + dd] = vmem[h*64 + dd];
        }
    }
}

// ---------------- fused attention megakernel ----------------
__global__ void __launch_bounds__(256) k_attn_all() {
    __shared__ float qs[8][64];
    __shared__ float sc[8][160];
    __shared__ int selS[8][8];
    __shared__ float sqs[16][65], sks[16][65], svs[16][65], saccs[16][64], ssc[16][17];
    __shared__ float smrow[16], slrow[16], salpha[16];

    int h = blockIdx.y;
    int tid = threadIdx.x;

    if (blockIdx.x < NN/8) {
        int w = tid >> 5, lane = tid & 31;
        int i = blockIdx.x*8 + w;
        int own = i >> 4;
        const float* qp = g_q + (h*NN + i)*64;
        qs[w][lane] = qp[lane]; qs[w][lane + 32] = qp[lane + 32];
        __syncwarp();
        const float4* q4 = (const float4*)qs[w];
        for (int j = lane; j <= own; j += 32) {
            const float4* kr = (const float4*)(g_ckf + (h*65 + j)*64);
            float acc = 0.f;
#pragma unroll
            for (int d4 = 0; d4 < 16; d4++) {
                float4 kv = kr[d4]; float4 qv = q4[d4];
                acc += qv.x*kv.x + qv.y*kv.y + qv.z*kv.z + qv.w*kv.w;
            }
            sc[w][j] = acc * SCALE;
        }
        __syncwarp();
        float m = -INFINITY;
        for (int j = lane; j <= own; j += 32) m = fmaxf(m, sc[w][j]);
#pragma unroll
        for (int o = 16; o > 0; o >>= 1) m = fmaxf(m, __shfl_xor_sync(0xFFFFFFFFu, m, o));
        float s = 0.f;
        for (int j = lane; j <= own; j += 32) { float e = __expf(sc[w][j] - m); sc[w][j] = e; s += e; }
#pragma unroll
        for (int o = 16; o > 0; o >>= 1) s += __shfl_xor_sync(0xFFFFFFFFu, s, o);
        float inv = 1.f / s;
        __syncwarp();
        float a0 = 0.f, a1 = 0.f;
#pragma unroll 4
        for (int j = 0; j <= own; j++) {
            float a = sc[w][j] * inv;
            const float* vr = g_cvf + (h*65 + j)*64;
            a0 += a * vr[lane]; a1 += a * vr[lane + 32];
        }
        g_cout[(h*NN + i)*64 + lane] = a0;
        g_cout[(h*NN + i)*64 + lane + 32] = a1;
        unsigned long long k0 = 0ULL, k1 = 0ULL;
        if (lane < own)
            k0 = ((unsigned long long)__float_as_uint(sc[w][1 + lane]) << 32)
               | (unsigned)(0xFFFFFFFFu - lane);
        if (lane + 32 < own)
            k1 = ((unsigned long long)__float_as_uint(sc[w][1 + lane + 32]) << 32)
               | (unsigned)(0xFFFFFFFFu - (lane + 32));
        int nv = 0;
#pragma unroll
        for (int t = 0; t < 8; t++) {
            unsigned long long mk = (k0 > k1) ? k0 : k1;
#pragma unroll
            for (int o = 16; o > 0; o >>= 1) {
                unsigned long long other = __shfl_xor_sync(0xFFFFFFFFu, mk, o);
                if (other > mk) mk = other;
            }
            if (mk) {
                int c = (int)(0xFFFFFFFFu - (unsigned)(mk & 0xFFFFFFFFu));
                if (k0 == mk) k0 = 0ULL;
                if (k1 == mk) k1 = 0ULL;
                if (lane == 0) selS[w][t] = c;
                nv = t + 1;
            } else if (lane == 0) selS[w][t] = 0;
        }
        __syncwarp();
        int nk = nv*16 + (i & 15) + 1;
        for (int kk = lane; kk < nk; kk += 32) {
            int tok = (kk < nv*16) ? selS[w][kk >> 4]*16 + (kk & 15) : own*16 + (kk - nv*16);
            const float4* kr = (const float4*)(g_k + (h*NN + tok)*64);
            float acc = 0.f;
#pragma unroll
            for (int d4 = 0; d4 < 16; d4++) {
                float4 kv = kr[d4]; float4 qv = q4[d4];
                acc += qv.x*kv.x + qv.y*kv.y + qv.z*kv.z + qv.w*kv.w;
            }
            sc[w][kk] = acc * SCALE;
        }
        __syncwarp();
        m = -INFINITY;
        for (int kk = lane; kk < nk; kk += 32) m = fmaxf(m, sc[w][kk]);
#pragma unroll
        for (int o = 16; o > 0; o >>= 1) m = fmaxf(m, __shfl_xor_sync(0xFFFFFFFFu, m, o));
        s = 0.f;
        for (int kk = lane; kk < nk; kk += 32) { float e = __expf(sc[w][kk] - m); sc[w][kk] = e; s += e; }
#pragma unroll
        for (int o = 16; o > 0; o >>= 1) s += __shfl_xor_sync(0xFFFFFFFFu, s, o);
        inv = 1.f / s;
        __syncwarp();
        a0 = 0.f; a1 = 0.f;
#pragma unroll 4
        for (int kk = 0; kk < nk; kk++) {
            int tok = (kk < nv*16) ? selS[w][kk >> 4]*16 + (kk & 15) : own*16 + (kk - nv*16);
            float a = sc[w][kk] * inv;
            const float* vr = g_v + (h*NN + tok)*64;
            a0 += a * vr[lane]; a1 += a * vr[lane + 32];
        }
        g_fout[(h*NN + i)*64 + lane] = a0;
        g_fout[(h*NN + i)*64 + lane + 32] = a1;
    } else {
        int qt = blockIdx.x - NN/8;
        int i0 = qt*16;
#pragma unroll
        for (int r = 0; r < 4; r++) {
            int idx = tid + r*256; int qi = idx >> 6, d = idx & 63;
            sqs[qi][d] = g_q[(h*NN + i0 + qi)*64 + d];
            saccs[qi][d] = 0.f;
        }
        if (tid < 16) { smrow[tid] = -INFINITY; slrow[tid] = 0.f; }
        __syncthreads();
        int t0 = (qt > 16) ? (qt - 16) : 0;
        for (int t = t0; t <= qt; t++) {
#pragma unroll
            for (int r = 0; r < 4; r++) {
                int idx = tid + r*256; int kj = idx >> 6, d = idx & 63;
                sks[kj][d] = g_k[(h*NN + t*16 + kj)*64 + d];
                svs[kj][d] = g_v[(h*NN + t*16 + kj)*64 + d];
            }
            __syncthreads();
            {
                int qi = tid >> 4, kj = tid & 15;
                int j = t*16 + kj, ii = i0 + qi;
                float s = 0.f;
#pragma unroll
                for (int d = 0; d < 64; d++) s += sqs[qi][d]*sks[kj][d];
                bool vis = (j <= ii) && (ii - j < 256);
                ssc[qi][kj] = vis ? s*SCALE : -INFINITY;
            }
            __syncthreads();
            if (tid < 16) {
                int qi = tid;
                float rm = -INFINITY;
                for (int kj = 0; kj < 16; kj++) rm = fmaxf(rm, ssc[qi][kj]);
                float nm = fmaxf(smrow[qi], rm);
                float al, rs = 0.f;
                if (nm == -INFINITY) {
                    al = 1.f;
                    for (int kj = 0; kj < 16; kj++) ssc[qi][kj] = 0.f;
                } else {
                    al = __expf(smrow[qi] - nm);
                    for (int kj = 0; kj < 16; kj++) {
                        float ee = __expf(ssc[qi][kj] - nm);
                        ssc[qi][kj] = ee; rs += ee;
                    }
                }
                smrow[qi] = nm; salpha[qi] = al; slrow[qi] = slrow[qi]*al + rs;
            }
            __syncthreads();
#pragma unroll
            for (int r = 0; r < 4; r++) {
                int idx = tid + r*256; int qi = idx >> 6, d = idx & 63;
                float a = saccs[qi][d]*salpha[qi];
#pragma unroll
                for (int kj = 0; kj < 16; kj++) a += ssc[qi][kj]*svs[kj][d];
                saccs[qi][d] = a;
            }
            __syncthreads();
        }
#pragma unroll
        for (int r = 0; r < 4; r++) {
            int idx = tid + r*256; int qi = idx >> 6, d = idx & 63;
            g_sout[(h*NN + i0 + qi)*64 + d] = saccs[qi][d] / slrow[qi];
        }
    }
}

// ---------------- gated combine -> bf16 hi/lo ----------------
__global__ void k_combine() {
    int n = blockIdx.x, c = threadIdx.x;
    int h = c >> 6, d = c & 63;
    const float* gl = g_gate + n*24 + h*3;
    float g0 = 1.f/(1.f + __expf(-gl[0]));
    float g1 = 1.f/(1.f + __expf(-gl[1]));
    float g2 = 1.f/(1.f + __expf(-gl[2]));
    int idx = (h*NN + n)*64 + d;
    float v = g0*g_cout[idx] + g1*g_fout[idx] + g2*g_sout[idx];
    __nv_bfloat16 hh, ll; split_bf(v, hh, ll);
    g_ohi[n*DIM + c] = hh; g_olo[n*DIM + c] = ll;
}

// ---------------- launch ----------------
extern "C" void kernel_launch(void* const* d_in, const int* in_sizes, int n_in,
                              void* d_out, int out_size) {
    const float* x    = (const float*)d_in[0];
    const float* x0   = (const float*)d_in[2];
    const float* lam  = (const float*)d_in[3];
    const float* Wq   = (const float*)d_in[4];
    const float* Wk   = (const float*)d_in[5];
    const float* Wv   = (const float*)d_in[6];
    const float* Wo   = (const float*)d_in[7];
    const float* Wg   = (const float*)d_in[8];
    const float* kpos = (const float*)d_in[9];
    const float* vpos = (const float*)d_in[10];
    const float* Wck  = (const float*)d_in[11];
    const float* bck  = (const float*)d_in[12];
    const float* Wcv  = (const float*)d_in[13];
    const float* bcv  = (const float*)d_in[14];
    const float* kmem = (const float*)d_in[15];
    const float* vmem = (const float*)d_in[16];
    const float* W1   = (const float*)d_in[17];
    const float* W2   = (const float*)d_in[18];
    float* out = (float*)d_out;

    float *p_xr, *p_x2;
    cudaGetSymbolAddress((void**)&p_xr,  g_xr);
    cudaGetSymbolAddress((void**)&p_x2,  g_x2);
    __nv_bfloat16 *p_xnh,*p_xnl,*p_ohi,*p_olo,*p_hhi,*p_hlo;
    __nv_bfloat16 *p_qkvTh,*p_qkvTl,*p_woTh,*p_woTl,*p_w1Th,*p_w1Tl,*p_w2Th,*p_w2Tl;
    cudaGetSymbolAddress((void**)&p_xnh, g_xnh);  cudaGetSymbolAddress((void**)&p_xnl, g_xnl);
    cudaGetSymbolAddress((void**)&p_ohi, g_ohi);  cudaGetSymbolAddress((void**)&p_olo, g_olo);
    cudaGetSymbolAddress((void**)&p_hhi, g_hhi);  cudaGetSymbolAddress((void**)&p_hlo, g_hlo);
    cudaGetSymbolAddress((void**)&p_qkvTh, g_wqkvTh); cudaGetSymbolAddress((void**)&p_qkvTl, g_wqkvTl);
    cudaGetSymbolAddress((void**)&p_woTh, g_woTh);   cudaGetSymbolAddress((void**)&p_woTl, g_woTl);
    cudaGetSymbolAddress((void**)&p_w1Th, g_w1Th);   cudaGetSymbolAddress((void**)&p_w1Tl, g_w1Tl);
    cudaGetSymbolAddress((void**)&p_w2Th, g_w2Th);   cudaGetSymbolAddress((void**)&p_w2Tl, g_w2Tl);

    const int SMB64 = 2*(32768 + 2*64*128);   // 98304
    const int SMB32 = 2*(32768 + 2*32*128);   // 81920
    const int SMCK  = 24576*4;                // 96KB for k_ckcv
    cudaFuncSetAttribute(hm_gemm<64,3>, cudaFuncAttributeMaxDynamicSharedMemorySize, SMB64);
    cudaFuncSetAttribute(hm_gemm<64,2>, cudaFuncAttributeMaxDynamicSharedMemorySize, SMB64);
    cudaFuncSetAttribute(hm_gemm<32,1>, cudaFuncAttributeMaxDynamicSharedMemorySize, SMB32);
    cudaFuncSetAttribute(k_ckcv, cudaFuncAttributeMaxDynamicSharedMemorySize, SMCK);

    k_convAll<<<3104, dim3(32,8)>>>(Wq, Wk, Wv, Wo, W1, W2, Wg);
    k_prelude<<<NN, 128>>>(x, x0, lam);

    // fused QKV+gates GEMM with rope/transpose epilogue: writes g_q/g_k/g_v/g_gate
    hm_gemm<64,3><<<dim3(25,8), 256, SMB64>>>(p_xnh, p_xnl, p_qkvTh, p_qkvTl,
                                              nullptr, nullptr, nullptr, nullptr, 512, 1600);

    k_ckcv<<<CC, 512, SMCK>>>(kpos, vpos, Wck, bck, Wcv, bcv, kmem, vmem);

    // fused attention: 128 attn tiles + 64 sliding tiles per head
    k_attn_all<<<dim3(NN/8 + NN/16, HH), 256>>>();
    k_combine<<<NN, 512>>>();

    // x2 = xr + o @ Wo
    hm_gemm<32,1><<<dim3(16,8), 256, SMB32>>>(p_ohi, p_olo, p_woTh, p_woTl,
                                              p_xr, p_x2, nullptr, nullptr, 512, 512);
    k_rmsnorm2<<<NN, 128>>>();
    // h = relu(xn2 @ W1)^2 -> bf16 hi/lo
    hm_gemm<64,2><<<dim3(32,8), 256, SMB64>>>(p_xnh, p_xnl, p_w1Th, p_w1Tl,
                                              nullptr, nullptr, p_hhi, p_hlo, 512, 2048);
    // out = x2 + h @ W2
    hm_gemm<32,1><<<dim3(16,8), 256, SMB32>>>(p_hhi, p_hlo, p_w2Th, p_w2Tl,
                                              p_x2, out, nullptr, nullptr, 2048, 512);
}

// round 15
// speedup vs baseline: 1.5918x; 1.5918x over previous
#include <cuda_runtime.h>
#include <cuda_bf16.h>
#include <stdint.h>
#include <math.h>

#define NN 1024
#define DIM 512
#define HH 8
#define DD 64
#define CC 64
#define SCALE 0.125f
#define NEGF -1e30f

// ---------------- scratch ----------------
__device__ float g_xr [NN*DIM];
__device__ __nv_bfloat16 g_xnh[NN*DIM], g_xnl[NN*DIM];
__device__ float g_gate[NN*24];
__device__ float g_q  [HH*NN*DD];
__device__ float g_k  [HH*NN*DD];
__device__ float g_v  [HH*NN*DD];
__device__ float g_ckf[HH*65*DD];
__device__ float g_cvf[HH*65*DD];
__device__ float g_cout[HH*NN*DD];
__device__ float g_fout[HH*NN*DD];
__device__ float g_sout[HH*NN*DD];
__device__ __nv_bfloat16 g_ohi[NN*DIM], g_olo[NN*DIM];
__device__ float g_x2 [NN*DIM];
__device__ __nv_bfloat16 g_hhi[NN*2048], g_hlo[NN*2048];
// transposed bf16 hi/lo weights: [Nout][K]
__device__ __nv_bfloat16 g_wqkvTh[1600*512], g_wqkvTl[1600*512];
__device__ __nv_bfloat16 g_woTh[512*512],    g_woTl[512*512];
__device__ __nv_bfloat16 g_w1Th[2048*512],   g_w1Tl[2048*512];
__device__ __nv_bfloat16 g_w2Th[512*2048],   g_w2Tl[512*2048];

// ---------------- helpers ----------------
__device__ __forceinline__ uint32_t smem_u32(const void* p) {
    uint32_t a;
    asm("{ .reg .u64 t; cvta.to.shared.u64 t, %1; cvt.u32.u64 %0, t; }" : "=r"(a) : "l"(p));
    return a;
}
__device__ __forceinline__ uint32_t swz(uint32_t off) { return off ^ ((off >> 3) & 0x70); }

#define LDSM_X4(r, addr) \
    asm volatile("ldmatrix.sync.aligned.m8n8.x4.shared.b16 {%0,%1,%2,%3}, [%4];" \
        : "=r"((r)[0]),"=r"((r)[1]),"=r"((r)[2]),"=r"((r)[3]) : "r"(addr))
#define LDSM_X2(r, addr) \
    asm volatile("ldmatrix.sync.aligned.m8n8.x2.shared.b16 {%0,%1}, [%2];" \
        : "=r"((r)[0]),"=r"((r)[1]) : "r"(addr))
#define CP16(dst, src) \
    asm volatile("cp.async.cg.shared.global [%0], [%1], 16;" :: "r"(dst), "l"(src))
#define CP_COMMIT() asm volatile("cp.async.commit_group;" ::: "memory")
#define CP_WAIT(n)  asm volatile("cp.async.wait_group %0;" :: "n"(n) : "memory")

__device__ __forceinline__ void mma16816(float* d, const uint32_t* a, const uint32_t* b) {
    asm volatile("mma.sync.aligned.m16n8k16.row.col.f32.bf16.bf16.f32 "
        "{%0,%1,%2,%3}, {%4,%5,%6,%7}, {%8,%9}, {%0,%1,%2,%3};"
        : "+f"(d[0]),"+f"(d[1]),"+f"(d[2]),"+f"(d[3])
        : "r"(a[0]),"r"(a[1]),"r"(a[2]),"r"(a[3]), "r"(b[0]),"r"(b[1]));
}
__device__ __forceinline__ void split_bf(float x, __nv_bfloat16& h, __nv_bfloat16& l) {
    h = __float2bfloat16(x);
    l = __float2bfloat16(x - __bfloat162float(h));
}

// ---------------- ONE fused weight transpose+split kernel ----------------
__global__ void k_convAll(const float* __restrict__ Wq, const float* __restrict__ Wk,
                          const float* __restrict__ Wv, const float* __restrict__ Wo,
                          const float* __restrict__ W1, const float* __restrict__ W2,
                          const float* __restrict__ Wg) {
    __shared__ __nv_bfloat16 th[32][33], tl[32][33];
    int t = blockIdx.x;
    const float* src; __nv_bfloat16 *dh, *dl;
    int K, N, rowOff; bool wg = false;
    if (t < 1024) {
        int s = t >> 8; t &= 255; K = 512; N = 512;
        if (s == 0)      { src = Wq; dh = g_wqkvTh; dl = g_wqkvTl; rowOff = 0; }
        else if (s == 1) { src = Wk; dh = g_wqkvTh; dl = g_wqkvTl; rowOff = 512; }
        else if (s == 2) { src = Wv; dh = g_wqkvTh; dl = g_wqkvTl; rowOff = 1024; }
        else             { src = Wo; dh = g_woTh;   dl = g_woTl;   rowOff = 0; }
    } else if (t < 2048) { t -= 1024; src = W1; dh = g_w1Th; dl = g_w1Tl; K = 512;  N = 2048; rowOff = 0; }
    else if (t < 3072)   { t -= 2048; src = W2; dh = g_w2Th; dl = g_w2Tl; K = 2048; N = 512;  rowOff = 0; }
    else { t -= 3072; src = Wg; dh = g_wqkvTh; dl = g_wqkvTl; K = 512; N = 64; rowOff = 1536; wg = true; }
    int tilesN = N >> 5;
    int tN = (t % tilesN)*32, tK = (t / tilesN)*32;
    int tx = threadIdx.x, ty = threadIdx.y;
#pragma unroll
    for (int r = 0; r < 4; r++) {
        int k = tK + ty + r*8, n = tN + tx;
        float v;
        if (wg) v = (n < 24) ? src[(size_t)k*24 + n] : 0.f;
        else    v = src[(size_t)k*N + n];
        __nv_bfloat16 h, l; split_bf(v, h, l);
        th[ty + r*8][tx] = h; tl[ty + r*8][tx] = l;
    }
    __syncthreads();
#pragma unroll
    for (int r = 0; r < 4; r++) {
        int n = tN + ty + r*8, k = tK + tx;
        size_t o = (size_t)(rowOff + n)*K + k;
        dh[o] = th[tx][ty + r*8];
        dl[o] = tl[tx][ty + r*8];
    }
}

// ---------------- HMMA GEMM with cp.async 2-stage pipeline ----------------
// MODE 1: Cf = acc + R.  MODE 2: Chi/Clo = split(relu(acc)^2).
// MODE 3 (QKV, TN=64): epilogue stages tile in smem, applies rope/transpose,
//         writes g_q/g_k/g_v/g_gate directly.
template<int TN, int MODE>
__global__ void __launch_bounds__(256, 2)
hm_gemm(const __nv_bfloat16* __restrict__ Ahi, const __nv_bfloat16* __restrict__ Alo,
        const __nv_bfloat16* __restrict__ Bhi, const __nv_bfloat16* __restrict__ Blo,
        const float* __restrict__ R, float* __restrict__ Cf,
        __nv_bfloat16* __restrict__ Chi, __nv_bfloat16* __restrict__ Clo,
        int K, int Nfull) {
    constexpr int NT = TN / 16;
    constexpr int STG = 32768 + 2*TN*128;
    extern __shared__ char dsm[];
    const uint32_t sb = smem_u32(dsm);
    int tid = threadIdx.x, wid = tid >> 5, lane = tid & 31;
    int wm = wid & 3, wn = wid >> 2;
    int rowBase = blockIdx.y*128, colBase = blockIdx.x*TN;

    float acc[2][NT][4];
#pragma unroll
    for (int mt = 0; mt < 2; mt++)
#pragma unroll
        for (int nt = 0; nt < NT; nt++)
#pragma unroll
            for (int r = 0; r < 4; r++) acc[mt][nt][r] = 0.f;

    auto issue = [&](int kc, int s) {
        uint32_t aH = sb + s*STG, aL = aH + 16384, bH = aH + 32768, bL = bH + TN*128;
        int rowL = tid >> 1, cb = (tid & 1)*4;
        const char* sAh = (const char*)(Ahi + ((size_t)(rowBase + rowL))*K + kc*64) + cb*16;
        const char* sAl = (const char*)(Alo + ((size_t)(rowBase + rowL))*K + kc*64) + cb*16;
#pragma unroll
        for (int j = 0; j < 4; j++) {
            uint32_t sw = swz((uint32_t)(rowL*128 + (cb + j)*16));
            CP16(aH + sw, sAh + j*16);
            CP16(aL + sw, sAl + j*16);
        }
#pragma unroll
        for (int it = 0; it < TN*8/256; it++) {
            int idx = tid + it*256;
            int n = idx >> 3, j = idx & 7;
            const char* sBh = (const char*)(Bhi + ((size_t)(colBase + n))*K + kc*64) + j*16;
            const char* sBl = (const char*)(Blo + ((size_t)(colBase + n))*K + kc*64) + j*16;
            uint32_t sw = swz((uint32_t)(n*128 + j*16));
            CP16(bH + sw, sBh);
            CP16(bL + sw, sBl);
        }
    };
    auto compute = [&](int s) {
        uint32_t A_H = sb + s*STG, A_L = A_H + 16384, B_H = A_H + 32768, B_L = B_H + TN*128;
#pragma unroll
        for (int ks = 0; ks < 4; ks++) {
            uint32_t ah[2][4], al[2][4], bh[NT][2], bl[NT][2];
#pragma unroll
            for (int mt = 0; mt < 2; mt++) {
                uint32_t off = swz((uint32_t)((wm*32 + mt*16 + (lane & 15))*128
                                              + ks*32 + (lane >> 4)*16));
                LDSM_X4(ah[mt], A_H + off);
                LDSM_X4(al[mt], A_L + off);
            }
#pragma unroll
            for (int nt = 0; nt < NT; nt++) {
                uint32_t off = swz((uint32_t)((wn*(TN/2) + nt*8 + (lane & 7))*128
                                              + ks*32 + ((lane >> 3) & 1)*16));
                LDSM_X2(bh[nt], B_H + off);
                LDSM_X2(bl[nt], B_L + off);
            }
#pragma unroll
            for (int mt = 0; mt < 2; mt++)
#pragma unroll
                for (int nt = 0; nt < NT; nt++) {
                    mma16816(acc[mt][nt], ah[mt], bh[nt]);
                    mma16816(acc[mt][nt], al[mt], bh[nt]);
                    mma16816(acc[mt][nt], ah[mt], bl[nt]);
                }
        }
    };

    int nCh = K >> 6;
    issue(0, 0); CP_COMMIT();
    for (int kc = 0; kc < nCh; kc++) {
        if (kc + 1 < nCh) { issue(kc + 1, (kc + 1) & 1); CP_COMMIT(); CP_WAIT(1); }
        else CP_WAIT(0);
        __syncthreads();
        compute(kc & 1);
        __syncthreads();
    }

    if (MODE == 3) {
        // stage tile in smem (fp32, padded rows), then rope/transpose/store
        float* ts = (float*)dsm;   // [128][66]
#pragma unroll
        for (int mt = 0; mt < 2; mt++)
#pragma unroll
            for (int nt = 0; nt < NT; nt++)
#pragma unroll
                for (int half = 0; half < 2; half++) {
                    int rl = wm*32 + mt*16 + (lane >> 2) + half*8;
                    int cl = wn*(TN/2) + nt*8 + (lane & 3)*2;
                    ts[rl*66 + cl]     = acc[mt][nt][half*2];
                    ts[rl*66 + cl + 1] = acc[mt][nt][half*2 + 1];
                }
        __syncthreads();
        if (colBase >= 1536) {
            for (int idx = tid; idx < 128*24; idx += 256) {
                int r = idx / 24, c = idx - r*24;
                g_gate[(rowBase + r)*24 + c] = ts[r*66 + c];
            }
        } else {
            int h = (colBase >> 6) & 7;
            int kind = colBase >> 9;         // 0=q, 1=k, 2=v
            if (kind == 2) {
                for (int idx = tid; idx < 8192; idx += 256) {
                    int r = idx >> 6, d = idx & 63;
                    g_v[(h*NN + rowBase + r)*64 + d] = ts[r*66 + d];
                }
            } else {
                float* dst = kind ? g_k : g_q;
                for (int idx = tid; idx < 4096; idx += 256) {
                    int r = idx >> 5, dp = idx & 31;
                    int n = rowBase + r;
                    float inv = expf(-(float)dp * (9.210340371976184f/32.f));
                    float ang = (float)n * inv;
                    float cs = cosf(ang), sn = sinf(ang);
                    float a = ts[r*66 + dp], b = ts[r*66 + dp + 32];
                    int o = (h*NN + n)*64;
                    dst[o + dp]      = a*cs - b*sn;
                    dst[o + dp + 32] = b*cs + a*sn;
                }
            }
        }
        return;
    }

#pragma unroll
    for (int mt = 0; mt < 2; mt++) {
#pragma unroll
        for (int nt = 0; nt < NT; nt++) {
#pragma unroll
            for (int half = 0; half < 2; half++) {
                int r = rowBase + wm*32 + mt*16 + (lane >> 2) + half*8;
#pragma unroll
                for (int q = 0; q < 2; q++) {
                    int c = colBase + wn*(TN/2) + nt*8 + (lane & 3)*2 + q;
                    float v = acc[mt][nt][half*2 + q];
                    size_t o = (size_t)r*Nfull + c;
                    if (MODE == 2) {
                        v = fmaxf(v, 0.f); v *= v;
                        __nv_bfloat16 h, l; split_bf(v, h, l);
                        Chi[o] = h; Clo[o] = l;
                    } else {
                        if (MODE == 1) v += R[o];
                        Cf[o] = v;
                    }
                }
            }
        }
    }
}

// ---------------- prelude ----------------
__global__ void k_prelude(const float* __restrict__ x, const float* __restrict__ x0,
                          const float* __restrict__ lam) {
    int n = blockIdx.x, tid = threadIdx.x;
    __shared__ float red[128];
    float l0 = lam[0], l1 = lam[1];
    float v[4]; float ss = 0.f;
#pragma unroll
    for (int r = 0; r < 4; r++) {
        int d = tid + r*128;
        float t = l0*x[n*DIM+d] + l1*x0[n*DIM+d];
        v[r] = t; g_xr[n*DIM+d] = t; ss += t*t;
    }
    red[tid] = ss; __syncthreads();
    for (int s = 64; s > 0; s >>= 1) { if (tid < s) red[tid] += red[tid+s]; __syncthreads(); }
    float rms = rsqrtf(red[0]*(1.f/512.f) + 1e-6f);
#pragma unroll
    for (int r = 0; r < 4; r++) {
        int d = tid + r*128; float t = v[r]*rms;
        __nv_bfloat16 h, l; split_bf(t, h, l);
        g_xnh[n*DIM+d] = h; g_xnl[n*DIM+d] = l;
    }
}

__global__ void k_rmsnorm2() {
    int n = blockIdx.x, tid = threadIdx.x;
    __shared__ float red[128];
    float v[4]; float ss = 0.f;
#pragma unroll
    for (int r = 0; r < 4; r++) { int d = tid + r*128; float t = g_x2[n*DIM+d]; v[r]=t; ss += t*t; }
    red[tid] = ss; __syncthreads();
    for (int s = 64; s > 0; s >>= 1) { if (tid < s) red[tid] += red[tid+s]; __syncthreads(); }
    float rms = rsqrtf(red[0]*(1.f/512.f) + 1e-6f);
#pragma unroll
    for (int r = 0; r < 4; r++) {
        int d = tid + r*128; float t = v[r]*rms;
        __nv_bfloat16 h, l; split_bf(t, h, l);
        g_xnh[n*DIM+d] = h; g_xnl[n*DIM+d] = l;
    }
}

// ---------------- compressed K/V: one block per c, all 8 heads, unrolled ----------------
__global__ void __launch_bounds__(512) k_ckcv(
        const float* __restrict__ kpos, const float* __restrict__ vpos,
        const float* __restrict__ Wck, const float* __restrict__ bck,
        const float* __restrict__ Wcv, const float* __restrict__ bcv,
        const float* __restrict__ kmem, const float* __restrict__ vmem) {
    extern __shared__ float sm[];
    float* kbs = sm;
    float* vbs = sm + 8192;
    float* redk = sm + 16384;
    float* redv = sm + 20480;
    int c = blockIdx.x, tid = threadIdx.x;
    for (int idx = tid; idx < 8192; idx += 512) {
        int h = idx >> 10, e = idx & 1023, j = e >> 6, d = e & 63;
        kbs[idx] = g_k[(h*NN + c*16 + j)*64 + d] + kpos[idx];
        vbs[idx] = g_v[(h*NN + c*16 + j)*64 + d] + vpos[idx];
    }
    __syncthreads();
    int part = tid >> 6, d = tid & 63;
    float ak[8] = {}, av[8] = {};
    int e0 = part*128;
    // unroll-by-4 with weight prefetch: breaks the per-iteration L2 latency chain
    for (int e = e0; e < e0 + 128; e += 4) {
        float wk[4], wv[4];
#pragma unroll
        for (int u = 0; u < 4; u++) {
            wk[u] = Wck[(e + u)*64 + d];
            wv[u] = Wcv[(e + u)*64 + d];
        }
#pragma unroll
        for (int u = 0; u < 4; u++) {
#pragma unroll
            for (int h = 0; h < 8; h++) {
                ak[h] += kbs[h*1024 + e + u]*wk[u];
                av[h] += vbs[h*1024 + e + u]*wv[u];
            }
        }
    }
#pragma unroll
    for (int h = 0; h < 8; h++) {
        redk[(part*8 + h)*64 + d] = ak[h];
        redv[(part*8 + h)*64 + d] = av[h];
    }
    __syncthreads();
    {
        int h = tid >> 6, dd = tid & 63;
        float sk = bck[dd], sv = bcv[dd];
#pragma unroll
        for (int p = 0; p < 8; p++) {
            sk += redk[(p*8 + h)*64 + dd];
            sv += redv[(p*8 + h)*64 + dd];
        }
        g_ckf[(h*65 + 1 + c)*64 + dd] = sk;
        g_cvf[(h*65 + 1 + c)*64 + dd] = sv;
        if (c == 0) {
            g_ckf[h*65*64 + dd] = kmem[h*64 + dd];
            g_cvf[h*65*64 + dd] = vmem[h*64 + dd];
        }
    }
}

// ---------------- fused attention megakernel ----------------
__global__ void __launch_bounds__(256) k_attn_all() {
    __shared__ float qs[8][64];
    __shared__ float sc[8][160];
    __shared__ int selS[8][8];
    __shared__ float sqs[16][65], sks[16][65], svs[16][65], saccs[16][64], ssc[16][17];
    __shared__ float smrow[16], slrow[16], salpha[16];

    int h = blockIdx.y;
    int tid = threadIdx.x;

    if (blockIdx.x < NN/8) {
        int w = tid >> 5, lane = tid & 31;
        int i = blockIdx.x*8 + w;
        int own = i >> 4;
        const float* qp = g_q + (h*NN + i)*64;
        qs[w][lane] = qp[lane]; qs[w][lane + 32] = qp[lane + 32];
        __syncwarp();
        const float4* q4 = (const float4*)qs[w];
        for (int j = lane; j <= own; j += 32) {
            const float4* kr = (const float4*)(g_ckf + (h*65 + j)*64);
            float acc = 0.f;
#pragma unroll
            for (int d4 = 0; d4 < 16; d4++) {
                float4 kv = kr[d4]; float4 qv = q4[d4];
                acc += qv.x*kv.x + qv.y*kv.y + qv.z*kv.z + qv.w*kv.w;
            }
            sc[w][j] = acc * SCALE;
        }
        __syncwarp();
        float m = -INFINITY;
        for (int j = lane; j <= own; j += 32) m = fmaxf(m, sc[w][j]);
#pragma unroll
        for (int o = 16; o > 0; o >>= 1) m = fmaxf(m, __shfl_xor_sync(0xFFFFFFFFu, m, o));
        float s = 0.f;
        for (int j = lane; j <= own; j += 32) { float e = __expf(sc[w][j] - m); sc[w][j] = e; s += e; }
#pragma unroll
        for (int o = 16; o > 0; o >>= 1) s += __shfl_xor_sync(0xFFFFFFFFu, s, o);
        float inv = 1.f / s;
        __syncwarp();
        float a0 = 0.f, a1 = 0.f;
#pragma unroll 4
        for (int j = 0; j <= own; j++) {
            float a = sc[w][j] * inv;
            const float* vr = g_cvf + (h*65 + j)*64;
            a0 += a * vr[lane]; a1 += a * vr[lane + 32];
        }
        g_cout[(h*NN + i)*64 + lane] = a0;
        g_cout[(h*NN + i)*64 + lane + 32] = a1;
        unsigned long long k0 = 0ULL, k1 = 0ULL;
        if (lane < own)
            k0 = ((unsigned long long)__float_as_uint(sc[w][1 + lane]) << 32)
               | (unsigned)(0xFFFFFFFFu - lane);
        if (lane + 32 < own)
            k1 = ((unsigned long long)__float_as_uint(sc[w][1 + lane + 32]) << 32)
               | (unsigned)(0xFFFFFFFFu - (lane + 32));
        int nv = 0;
#pragma unroll
        for (int t = 0; t < 8; t++) {
            unsigned long long mk = (k0 > k1) ? k0 : k1;
#pragma unroll
            for (int o = 16; o > 0; o >>= 1) {
                unsigned long long other = __shfl_xor_sync(0xFFFFFFFFu, mk, o);
                if (other > mk) mk = other;
            }
            if (mk) {
                int c = (int)(0xFFFFFFFFu - (unsigned)(mk & 0xFFFFFFFFu));
                if (k0 == mk) k0 = 0ULL;
                if (k1 == mk) k1 = 0ULL;
                if (lane == 0) selS[w][t] = c;
                nv = t + 1;
            } else if (lane == 0) selS[w][t] = 0;
        }
        __syncwarp();
        int nk = nv*16 + (i & 15) + 1;
        for (int kk = lane; kk < nk; kk += 32) {
            int tok = (kk < nv*16) ? selS[w][kk >> 4]*16 + (kk & 15) : own*16 + (kk - nv*16);
            const float4* kr = (const float4*)(g_k + (h*NN + tok)*64);
            float acc = 0.f;
#pragma unroll
            for (int d4 = 0; d4 < 16; d4++) {
                float4 kv = kr[d4]; float4 qv = q4[d4];
                acc += qv.x*kv.x + qv.y*kv.y + qv.z*kv.z + qv.w*kv.w;
            }
            sc[w][kk] = acc * SCALE;
        }
        __syncwarp();
        m = -INFINITY;
        for (int kk = lane; kk < nk; kk += 32) m = fmaxf(m, sc[w][kk]);
#pragma unroll
        for (int o = 16; o > 0; o >>= 1) m = fmaxf(m, __shfl_xor_sync(0xFFFFFFFFu, m, o));
        s = 0.f;
        for (int kk = lane; kk < nk; kk += 32) { float e = __expf(sc[w][kk] - m); sc[w][kk] = e; s += e; }
#pragma unroll
        for (int o = 16; o > 0; o >>= 1) s += __shfl_xor_sync(0xFFFFFFFFu, s, o);
        inv = 1.f / s;
        __syncwarp();
        a0 = 0.f; a1 = 0.f;
#pragma unroll 4
        for (int kk = 0; kk < nk; kk++) {
            int tok = (kk < nv*16) ? selS[w][kk >> 4]*16 + (kk & 15) : own*16 + (kk - nv*16);
            float a = sc[w][kk] * inv;
            const float* vr = g_v + (h*NN + tok)*64;
            a0 += a * vr[lane]; a1 += a * vr[lane + 32];
        }
        g_fout[(h*NN + i)*64 + lane] = a0;
        g_fout[(h*NN + i)*64 + lane + 32] = a1;
    } else {
        int qt = blockIdx.x - NN/8;
        int i0 = qt*16;
#pragma unroll
        for (int r = 0; r < 4; r++) {
            int idx = tid + r*256; int qi = idx >> 6, d = idx & 63;
            sqs[qi][d] = g_q[(h*NN + i0 + qi)*64 + d];
            saccs[qi][d] = 0.f;
        }
        if (tid < 16) { smrow[tid] = -INFINITY; slrow[tid] = 0.f; }
        __syncthreads();
        int t0 = (qt > 16) ? (qt - 16) : 0;
        for (int t = t0; t <= qt; t++) {
#pragma unroll
            for (int r = 0; r < 4; r++) {
                int idx = tid + r*256; int kj = idx >> 6, d = idx & 63;
                sks[kj][d] = g_k[(h*NN + t*16 + kj)*64 + d];
                svs[kj][d] = g_v[(h*NN + t*16 + kj)*64 + d];
            }
            __syncthreads();
            {
                int qi = tid >> 4, kj = tid & 15;
                int j = t*16 + kj, ii = i0 + qi;
                float s = 0.f;
#pragma unroll
                for (int d = 0; d < 64; d++) s += sqs[qi][d]*sks[kj][d];
                bool vis = (j <= ii) && (ii - j < 256);
                ssc[qi][kj] = vis ? s*SCALE : -INFINITY;
            }
            __syncthreads();
            if (tid < 16) {
                int qi = tid;
                float rm = -INFINITY;
                for (int kj = 0; kj < 16; kj++) rm = fmaxf(rm, ssc[qi][kj]);
                float nm = fmaxf(smrow[qi], rm);
                float al, rs = 0.f;
                if (nm == -INFINITY) {
                    al = 1.f;
                    for (int kj = 0; kj < 16; kj++) ssc[qi][kj] = 0.f;
                } else {
                    al = __expf(smrow[qi] - nm);
                    for (int kj = 0; kj < 16; kj++) {
                        float ee = __expf(ssc[qi][kj] - nm);
                        ssc[qi][kj] = ee; rs += ee;
                    }
                }
                smrow[qi] = nm; salpha[qi] = al; slrow[qi] = slrow[qi]*al + rs;
            }
            __syncthreads();
#pragma unroll
            for (int r = 0; r < 4; r++) {
                int idx = tid + r*256; int qi = idx >> 6, d = idx & 63;
                float a = saccs[qi][d]*salpha[qi];
#pragma unroll
                for (int kj = 0; kj < 16; kj++) a += ssc[qi][kj]*svs[kj][d];
                saccs[qi][d] = a;
            }
            __syncthreads();
        }
#pragma unroll
        for (int r = 0; r < 4; r++) {
            int idx = tid + r*256; int qi = idx >> 6, d = idx & 63;
            g_sout[(h*NN + i0 + qi)*64 + d] = saccs[qi][d] / slrow[qi];
        }
    }
}

// ---------------- gated combine -> bf16 hi/lo ----------------
__global__ void k_combine() {
    int n = blockIdx.x, c = threadIdx.x;
    int h = c >> 6, d = c & 63;
    const float* gl = g_gate + n*24 + h*3;
    float g0 = 1.f/(1.f + __expf(-gl[0]));
    float g1 = 1.f/(1.f + __expf(-gl[1]));
    float g2 = 1.f/(1.f + __expf(-gl[2]));
    int idx = (h*NN + n)*64 + d;
    float v = g0*g_cout[idx] + g1*g_fout[idx] + g2*g_sout[idx];
    __nv_bfloat16 hh, ll; split_bf(v, hh, ll);
    g_ohi[n*DIM + c] = hh; g_olo[n*DIM + c] = ll;
}

// ---------------- launch ----------------
extern "C" void kernel_launch(void* const* d_in, const int* in_sizes, int n_in,
                              void* d_out, int out_size) {
    const float* x    = (const float*)d_in[0];
    const float* x0   = (const float*)d_in[2];
    const float* lam  = (const float*)d_in[3];
    const float* Wq   = (const float*)d_in[4];
    const float* Wk   = (const float*)d_in[5];
    const float* Wv   = (const float*)d_in[6];
    const float* Wo   = (const float*)d_in[7];
    const float* Wg   = (const float*)d_in[8];
    const float* kpos = (const float*)d_in[9];
    const float* vpos = (const float*)d_in[10];
    const float* Wck  = (const float*)d_in[11];
    const float* bck  = (const float*)d_in[12];
    const float* Wcv  = (const float*)d_in[13];
    const float* bcv  = (const float*)d_in[14];
    const float* kmem = (const float*)d_in[15];
    const float* vmem = (const float*)d_in[16];
    const float* W1   = (const float*)d_in[17];
    const float* W2   = (const float*)d_in[18];
    float* out = (float*)d_out;

    float *p_xr, *p_x2;
    cudaGetSymbolAddress((void**)&p_xr,  g_xr);
    cudaGetSymbolAddress((void**)&p_x2,  g_x2);
    __nv_bfloat16 *p_xnh,*p_xnl,*p_ohi,*p_olo,*p_hhi,*p_hlo;
    __nv_bfloat16 *p_qkvTh,*p_qkvTl,*p_woTh,*p_woTl,*p_w1Th,*p_w1Tl,*p_w2Th,*p_w2Tl;
    cudaGetSymbolAddress((void**)&p_xnh, g_xnh);  cudaGetSymbolAddress((void**)&p_xnl, g_xnl);
    cudaGetSymbolAddress((void**)&p_ohi, g_ohi);  cudaGetSymbolAddress((void**)&p_olo, g_olo);
    cudaGetSymbolAddress((void**)&p_hhi, g_hhi);  cudaGetSymbolAddress((void**)&p_hlo, g_hlo);
    cudaGetSymbolAddress((void**)&p_qkvTh, g_wqkvTh); cudaGetSymbolAddress((void**)&p_qkvTl, g_wqkvTl);
    cudaGetSymbolAddress((void**)&p_woTh, g_woTh);   cudaGetSymbolAddress((void**)&p_woTl, g_woTl);
    cudaGetSymbolAddress((void**)&p_w1Th, g_w1Th);   cudaGetSymbolAddress((void**)&p_w1Tl, g_w1Tl);
    cudaGetSymbolAddress((void**)&p_w2Th, g_w2Th);   cudaGetSymbolAddress((void**)&p_w2Tl, g_w2Tl);

    const int SMB64 = 2*(32768 + 2*64*128);   // 98304
    const int SMB32 = 2*(32768 + 2*32*128);   // 81920
    const int SMCK  = 24576*4;                // 96KB for k_ckcv
    cudaFuncSetAttribute(hm_gemm<64,3>, cudaFuncAttributeMaxDynamicSharedMemorySize, SMB64);
    cudaFuncSetAttribute(hm_gemm<64,2>, cudaFuncAttributeMaxDynamicSharedMemorySize, SMB64);
    cudaFuncSetAttribute(hm_gemm<32,1>, cudaFuncAttributeMaxDynamicSharedMemorySize, SMB32);
    cudaFuncSetAttribute(k_ckcv, cudaFuncAttributeMaxDynamicSharedMemorySize, SMCK);

    k_convAll<<<3104, dim3(32,8)>>>(Wq, Wk, Wv, Wo, W1, W2, Wg);
    k_prelude<<<NN, 128>>>(x, x0, lam);

    // fused QKV+gates GEMM with rope/transpose epilogue: writes g_q/g_k/g_v/g_gate
    hm_gemm<64,3><<<dim3(25,8), 256, SMB64>>>(p_xnh, p_xnl, p_qkvTh, p_qkvTl,
                                              nullptr, nullptr, nullptr, nullptr, 512, 1600);

    k_ckcv<<<CC, 512, SMCK>>>(kpos, vpos, Wck, bck, Wcv, bcv, kmem, vmem);

    // fused attention: 128 attn tiles + 64 sliding tiles per head
    k_attn_all<<<dim3(NN/8 + NN/16, HH), 256>>>();
    k_combine<<<NN, 512>>>();

    // x2 = xr + o @ Wo
    hm_gemm<32,1><<<dim3(16,8), 256, SMB32>>>(p_ohi, p_olo, p_woTh, p_woTl,
                                              p_xr, p_x2, nullptr, nullptr, 512, 512);
    k_rmsnorm2<<<NN, 128>>>();
    // h = relu(xn2 @ W1)^2 -> bf16 hi/lo
    hm_gemm<64,2><<<dim3(32,8), 256, SMB64>>>(p_xnh, p_xnl, p_w1Th, p_w1Tl,
                                              nullptr, nullptr, p_hhi, p_hlo, 512, 2048);
    // out = x2 + h @ W2
    hm_gemm<32,1><<<dim3(16,8), 256, SMB32>>>(p_hhi, p_hlo, p_w2Th, p_w2Tl,
                                              p_x2, out, nullptr, nullptr, 2048, 512);
}

// round 16
// speedup vs baseline: 1.6211x; 1.0184x over previous
#include <cuda_runtime.h>
#include <cuda_bf16.h>
#include <stdint.h>
#include <math.h>

#define NN 1024
#define DIM 512
#define HH 8
#define DD 64
#define CC 64
#define SCALE 0.125f
#define NEGF -1e30f

// ---------------- scratch ----------------
__device__ float g_xr [NN*DIM];
__device__ __nv_bfloat16 g_xnh[NN*DIM], g_xnl[NN*DIM];
__device__ float g_gate[NN*24];
__device__ float g_q  [HH*NN*DD];
__device__ float g_k  [HH*NN*DD];
__device__ float g_v  [HH*NN*DD];
__device__ float g_ckf[HH*65*DD];
__device__ float g_cvf[HH*65*DD];
__device__ float g_pck[HH*CC*8*DD];   // partial ck: [h][c][slice][d]
__device__ float g_pcv[HH*CC*8*DD];
__device__ float g_cout[HH*NN*DD];
__device__ float g_fout[HH*NN*DD];
__device__ float g_sout[HH*NN*DD];
__device__ __nv_bfloat16 g_ohi[NN*DIM], g_olo[NN*DIM];
__device__ float g_x2 [NN*DIM];
__device__ __nv_bfloat16 g_hhi[NN*2048], g_hlo[NN*2048];
// transposed bf16 hi/lo weights: [Nout][K]
__device__ __nv_bfloat16 g_wqkvTh[1600*512], g_wqkvTl[1600*512];
__device__ __nv_bfloat16 g_woTh[512*512],    g_woTl[512*512];
__device__ __nv_bfloat16 g_w1Th[2048*512],   g_w1Tl[2048*512];
__device__ __nv_bfloat16 g_w2Th[512*2048],   g_w2Tl[512*2048];

// ---------------- helpers ----------------
__device__ __forceinline__ uint32_t smem_u32(const void* p) {
    uint32_t a;
    asm("{ .reg .u64 t; cvta.to.shared.u64 t, %1; cvt.u32.u64 %0, t; }" : "=r"(a) : "l"(p));
    return a;
}
__device__ __forceinline__ uint32_t swz(uint32_t off) { return off ^ ((off >> 3) & 0x70); }

#define LDSM_X4(r, addr) \
    asm volatile("ldmatrix.sync.aligned.m8n8.x4.shared.b16 {%0,%1,%2,%3}, [%4];" \
        : "=r"((r)[0]),"=r"((r)[1]),"=r"((r)[2]),"=r"((r)[3]) : "r"(addr))
#define LDSM_X2(r, addr) \
    asm volatile("ldmatrix.sync.aligned.m8n8.x2.shared.b16 {%0,%1}, [%2];" \
        : "=r"((r)[0]),"=r"((r)[1]) : "r"(addr))
#define CP16(dst, src) \
    asm volatile("cp.async.cg.shared.global [%0], [%1], 16;" :: "r"(dst), "l"(src))
#define CP_COMMIT() asm volatile("cp.async.commit_group;" ::: "memory")
#define CP_WAIT(n)  asm volatile("cp.async.wait_group %0;" :: "n"(n) : "memory")

__device__ __forceinline__ void mma16816(float* d, const uint32_t* a, const uint32_t* b) {
    asm volatile("mma.sync.aligned.m16n8k16.row.col.f32.bf16.bf16.f32 "
        "{%0,%1,%2,%3}, {%4,%5,%6,%7}, {%8,%9}, {%0,%1,%2,%3};"
        : "+f"(d[0]),"+f"(d[1]),"+f"(d[2]),"+f"(d[3])
        : "r"(a[0]),"r"(a[1]),"r"(a[2]),"r"(a[3]), "r"(b[0]),"r"(b[1]));
}
__device__ __forceinline__ void split_bf(float x, __nv_bfloat16& h, __nv_bfloat16& l) {
    h = __float2bfloat16(x);
    l = __float2bfloat16(x - __bfloat162float(h));
}

// ---------------- ONE fused weight transpose+split kernel ----------------
__global__ void k_convAll(const float* __restrict__ Wq, const float* __restrict__ Wk,
                          const float* __restrict__ Wv, const float* __restrict__ Wo,
                          const float* __restrict__ W1, const float* __restrict__ W2,
                          const float* __restrict__ Wg) {
    __shared__ __nv_bfloat16 th[32][33], tl[32][33];
    int t = blockIdx.x;
    const float* src; __nv_bfloat16 *dh, *dl;
    int K, N, rowOff; bool wg = false;
    if (t < 1024) {
        int s = t >> 8; t &= 255; K = 512; N = 512;
        if (s == 0)      { src = Wq; dh = g_wqkvTh; dl = g_wqkvTl; rowOff = 0; }
        else if (s == 1) { src = Wk; dh = g_wqkvTh; dl = g_wqkvTl; rowOff = 512; }
        else if (s == 2) { src = Wv; dh = g_wqkvTh; dl = g_wqkvTl; rowOff = 1024; }
        else             { src = Wo; dh = g_woTh;   dl = g_woTl;   rowOff = 0; }
    } else if (t < 2048) { t -= 1024; src = W1; dh = g_w1Th; dl = g_w1Tl; K = 512;  N = 2048; rowOff = 0; }
    else if (t < 3072)   { t -= 2048; src = W2; dh = g_w2Th; dl = g_w2Tl; K = 2048; N = 512;  rowOff = 0; }
    else { t -= 3072; src = Wg; dh = g_wqkvTh; dl = g_wqkvTl; K = 512; N = 64; rowOff = 1536; wg = true; }
    int tilesN = N >> 5;
    int tN = (t % tilesN)*32, tK = (t / tilesN)*32;
    int tx = threadIdx.x, ty = threadIdx.y;
#pragma unroll
    for (int r = 0; r < 4; r++) {
        int k = tK + ty + r*8, n = tN + tx;
        float v;
        if (wg) v = (n < 24) ? src[(size_t)k*24 + n] : 0.f;
        else    v = src[(size_t)k*N + n];
        __nv_bfloat16 h, l; split_bf(v, h, l);
        th[ty + r*8][tx] = h; tl[ty + r*8][tx] = l;
    }
    __syncthreads();
#pragma unroll
    for (int r = 0; r < 4; r++) {
        int n = tN + ty + r*8, k = tK + tx;
        size_t o = (size_t)(rowOff + n)*K + k;
        dh[o] = th[tx][ty + r*8];
        dl[o] = tl[tx][ty + r*8];
    }
}

// ---------------- HMMA GEMM with cp.async 2-stage pipeline ----------------
// MODE 1: Cf = acc + R.  MODE 2: Chi/Clo = split(relu(acc)^2).
// MODE 3 (QKV, TN=64): rope/transpose epilogue.
template<int TN, int MODE>
__global__ void __launch_bounds__(256, 2)
hm_gemm(const __nv_bfloat16* __restrict__ Ahi, const __nv_bfloat16* __restrict__ Alo,
        const __nv_bfloat16* __restrict__ Bhi, const __nv_bfloat16* __restrict__ Blo,
        const float* __restrict__ R, float* __restrict__ Cf,
        __nv_bfloat16* __restrict__ Chi, __nv_bfloat16* __restrict__ Clo,
        int K, int Nfull) {
    constexpr int NT = TN / 16;
    constexpr int STG = 32768 + 2*TN*128;
    extern __shared__ char dsm[];
    const uint32_t sb = smem_u32(dsm);
    int tid = threadIdx.x, wid = tid >> 5, lane = tid & 31;
    int wm = wid & 3, wn = wid >> 2;
    int rowBase = blockIdx.y*128, colBase = blockIdx.x*TN;

    float acc[2][NT][4];
#pragma unroll
    for (int mt = 0; mt < 2; mt++)
#pragma unroll
        for (int nt = 0; nt < NT; nt++)
#pragma unroll
            for (int r = 0; r < 4; r++) acc[mt][nt][r] = 0.f;

    auto issue = [&](int kc, int s) {
        uint32_t aH = sb + s*STG, aL = aH + 16384, bH = aH + 32768, bL = bH + TN*128;
        int rowL = tid >> 1, cb = (tid & 1)*4;
        const char* sAh = (const char*)(Ahi + ((size_t)(rowBase + rowL))*K + kc*64) + cb*16;
        const char* sAl = (const char*)(Alo + ((size_t)(rowBase + rowL))*K + kc*64) + cb*16;
#pragma unroll
        for (int j = 0; j < 4; j++) {
            uint32_t sw = swz((uint32_t)(rowL*128 + (cb + j)*16));
            CP16(aH + sw, sAh + j*16);
            CP16(aL + sw, sAl + j*16);
        }
#pragma unroll
        for (int it = 0; it < TN*8/256; it++) {
            int idx = tid + it*256;
            int n = idx >> 3, j = idx & 7;
            const char* sBh = (const char*)(Bhi + ((size_t)(colBase + n))*K + kc*64) + j*16;
            const char* sBl = (const char*)(Blo + ((size_t)(colBase + n))*K + kc*64) + j*16;
            uint32_t sw = swz((uint32_t)(n*128 + j*16));
            CP16(bH + sw, sBh);
            CP16(bL + sw, sBl);
        }
    };
    auto compute = [&](int s) {
        uint32_t A_H = sb + s*STG, A_L = A_H + 16384, B_H = A_H + 32768, B_L = B_H + TN*128;
#pragma unroll
        for (int ks = 0; ks < 4; ks++) {
            uint32_t ah[2][4], al[2][4], bh[NT][2], bl[NT][2];
#pragma unroll
            for (int mt = 0; mt < 2; mt++) {
                uint32_t off = swz((uint32_t)((wm*32 + mt*16 + (lane & 15))*128
                                              + ks*32 + (lane >> 4)*16));
                LDSM_X4(ah[mt], A_H + off);
                LDSM_X4(al[mt], A_L + off);
            }
#pragma unroll
            for (int nt = 0; nt < NT; nt++) {
                uint32_t off = swz((uint32_t)((wn*(TN/2) + nt*8 + (lane & 7))*128
                                              + ks*32 + ((lane >> 3) & 1)*16));
                LDSM_X2(bh[nt], B_H + off);
                LDSM_X2(bl[nt], B_L + off);
            }
#pragma unroll
            for (int mt = 0; mt < 2; mt++)
#pragma unroll
                for (int nt = 0; nt < NT; nt++) {
                    mma16816(acc[mt][nt], ah[mt], bh[nt]);
                    mma16816(acc[mt][nt], al[mt], bh[nt]);
                    mma16816(acc[mt][nt], ah[mt], bl[nt]);
                }
        }
    };

    int nCh = K >> 6;
    issue(0, 0); CP_COMMIT();
    for (int kc = 0; kc < nCh; kc++) {
        if (kc + 1 < nCh) { issue(kc + 1, (kc + 1) & 1); CP_COMMIT(); CP_WAIT(1); }
        else CP_WAIT(0);
        __syncthreads();
        compute(kc & 1);
        __syncthreads();
    }

    if (MODE == 3) {
        float* ts = (float*)dsm;   // [128][66]
#pragma unroll
        for (int mt = 0; mt < 2; mt++)
#pragma unroll
            for (int nt = 0; nt < NT; nt++)
#pragma unroll
                for (int half = 0; half < 2; half++) {
                    int rl = wm*32 + mt*16 + (lane >> 2) + half*8;
                    int cl = wn*(TN/2) + nt*8 + (lane & 3)*2;
                    ts[rl*66 + cl]     = acc[mt][nt][half*2];
                    ts[rl*66 + cl + 1] = acc[mt][nt][half*2 + 1];
                }
        __syncthreads();
        if (colBase >= 1536) {
            for (int idx = tid; idx < 128*24; idx += 256) {
                int r = idx / 24, c = idx - r*24;
                g_gate[(rowBase + r)*24 + c] = ts[r*66 + c];
            }
        } else {
            int h = (colBase >> 6) & 7;
            int kind = colBase >> 9;         // 0=q, 1=k, 2=v
            if (kind == 2) {
                for (int idx = tid; idx < 8192; idx += 256) {
                    int r = idx >> 6, d = idx & 63;
                    g_v[(h*NN + rowBase + r)*64 + d] = ts[r*66 + d];
                }
            } else {
                float* dst = kind ? g_k : g_q;
                for (int idx = tid; idx < 4096; idx += 256) {
                    int r = idx >> 5, dp = idx & 31;
                    int n = rowBase + r;
                    float inv = expf(-(float)dp * (9.210340371976184f/32.f));
                    float ang = (float)n * inv;
                    float cs = cosf(ang), sn = sinf(ang);
                    float a = ts[r*66 + dp], b = ts[r*66 + dp + 32];
                    int o = (h*NN + n)*64;
                    dst[o + dp]      = a*cs - b*sn;
                    dst[o + dp + 32] = b*cs + a*sn;
                }
            }
        }
        return;
    }

#pragma unroll
    for (int mt = 0; mt < 2; mt++) {
#pragma unroll
        for (int nt = 0; nt < NT; nt++) {
#pragma unroll
            for (int half = 0; half < 2; half++) {
                int r = rowBase + wm*32 + mt*16 + (lane >> 2) + half*8;
#pragma unroll
                for (int q = 0; q < 2; q++) {
                    int c = colBase + wn*(TN/2) + nt*8 + (lane & 3)*2 + q;
                    float v = acc[mt][nt][half*2 + q];
                    size_t o = (size_t)r*Nfull + c;
                    if (MODE == 2) {
                        v = fmaxf(v, 0.f); v *= v;
                        __nv_bfloat16 h, l; split_bf(v, h, l);
                        Chi[o] = h; Clo[o] = l;
                    } else {
                        if (MODE == 1) v += R[o];
                        Cf[o] = v;
                    }
                }
            }
        }
    }
}

// ---------------- prelude ----------------
__global__ void k_prelude(const float* __restrict__ x, const float* __restrict__ x0,
                          const float* __restrict__ lam) {
    int n = blockIdx.x, tid = threadIdx.x;
    __shared__ float red[128];
    float l0 = lam[0], l1 = lam[1];
    float v[4]; float ss = 0.f;
#pragma unroll
    for (int r = 0; r < 4; r++) {
        int d = tid + r*128;
        float t = l0*x[n*DIM+d] + l1*x0[n*DIM+d];
        v[r] = t; g_xr[n*DIM+d] = t; ss += t*t;
    }
    red[tid] = ss; __syncthreads();
    for (int s = 64; s > 0; s >>= 1) { if (tid < s) red[tid] += red[tid+s]; __syncthreads(); }
    float rms = rsqrtf(red[0]*(1.f/512.f) + 1e-6f);
#pragma unroll
    for (int r = 0; r < 4; r++) {
        int d = tid + r*128; float t = v[r]*rms;
        __nv_bfloat16 h, l; split_bf(t, h, l);
        g_xnh[n*DIM+d] = h; g_xnl[n*DIM+d] = l;
    }
}

__global__ void k_rmsnorm2() {
    int n = blockIdx.x, tid = threadIdx.x;
    __shared__ float red[128];
    float v[4]; float ss = 0.f;
#pragma unroll
    for (int r = 0; r < 4; r++) { int d = tid + r*128; float t = g_x2[n*DIM+d]; v[r]=t; ss += t*t; }
    red[tid] = ss; __syncthreads();
    for (int s = 64; s > 0; s >>= 1) { if (tid < s) red[tid] += red[tid+s]; __syncthreads(); }
    float rms = rsqrtf(red[0]*(1.f/512.f) + 1e-6f);
#pragma unroll
    for (int r = 0; r < 4; r++) {
        int d = tid + r*128; float t = v[r]*rms;
        __nv_bfloat16 h, l; split_bf(t, h, l);
        g_xnh[n*DIM+d] = h; g_xnl[n*DIM+d] = l;
    }
}

// ---------------- compressed K/V partial: grid (64 c, 8 slice), 512 thr ----------------
__global__ void __launch_bounds__(512) k_ckcv(
        const float* __restrict__ kpos, const float* __restrict__ vpos,
        const float* __restrict__ Wck, const float* __restrict__ Wcv) {
    __shared__ float kbs[8][128], vbs[8][128];       // 8KB
    __shared__ float redk[8][8][64], redv[8][8][64]; // 32KB
    int c = blockIdx.x, s = blockIdx.y, tid = threadIdx.x;
    for (int idx = tid; idx < 1024; idx += 512) {
        int h = idx >> 7, el = idx & 127;
        int j = s*2 + (el >> 6), dd = el & 63;
        kbs[h][el] = g_k[(h*NN + c*16 + j)*64 + dd] + kpos[h*1024 + s*128 + el];
        vbs[h][el] = g_v[(h*NN + c*16 + j)*64 + dd] + vpos[h*1024 + s*128 + el];
    }
    __syncthreads();
    int part = tid >> 6, d = tid & 63;
    float ak[8] = {}, av[8] = {};
    int e0 = part*16;
#pragma unroll
    for (int e = 0; e < 16; e++) {
        float wk = Wck[(s*128 + e0 + e)*64 + d];
        float wv = Wcv[(s*128 + e0 + e)*64 + d];
#pragma unroll
        for (int h = 0; h < 8; h++) {
            ak[h] += kbs[h][e0 + e]*wk;
            av[h] += vbs[h][e0 + e]*wv;
        }
    }
#pragma unroll
    for (int h = 0; h < 8; h++) {
        redk[part][h][d] = ak[h];
        redv[part][h][d] = av[h];
    }
    __syncthreads();
    {
        int h = tid >> 6, dd = tid & 63;
        float sk = 0.f, sv = 0.f;
#pragma unroll
        for (int p = 0; p < 8; p++) {
            sk += redk[p][h][dd];
            sv += redv[p][h][dd];
        }
        size_t o = (size_t)(((h*CC + c)*8 + s))*64 + dd;
        g_pck[o] = sk; g_pcv[o] = sv;
    }
}

// reduce slices + bias + kmem/vmem: grid 64 c, 512 thr (h x d)
__global__ void __launch_bounds__(512) k_ckred(
        const float* __restrict__ bck, const float* __restrict__ bcv,
        const float* __restrict__ kmem, const float* __restrict__ vmem) {
    int c = blockIdx.x, tid = threadIdx.x;
    int h = tid >> 6, d = tid & 63;
    size_t base = (size_t)((h*CC + c)*8)*64 + d;
    float sk = bck[d], sv = bcv[d];
#pragma unroll
    for (int s = 0; s < 8; s++) {
        sk += g_pck[base + s*64];
        sv += g_pcv[base + s*64];
    }
    g_ckf[(h*65 + 1 + c)*64 + d] = sk;
    g_cvf[(h*65 + 1 + c)*64 + d] = sv;
    if (c == 0) {
        g_ckf[h*65*64 + d] = kmem[h*64 + d];
        g_cvf[h*65*64 + d] = vmem[h*64 + d];
    }
}

// ---------------- fused attention megakernel ----------------
__global__ void __launch_bounds__(256) k_attn_all() {
    __shared__ float qs[8][64];
    __shared__ float sc[8][160];
    __shared__ int selS[8][8];
    __shared__ float sqs[16][65], sks[16][65], svs[16][65], saccs[16][64], ssc[16][17];
    __shared__ float smrow[16], slrow[16], salpha[16];

    int h = blockIdx.y;
    int tid = threadIdx.x;

    if (blockIdx.x < NN/8) {
        int w = tid >> 5, lane = tid & 31;
        int i = blockIdx.x*8 + w;
        int own = i >> 4;
        const float* qp = g_q + (h*NN + i)*64;
        qs[w][lane] = qp[lane]; qs[w][lane + 32] = qp[lane + 32];
        __syncwarp();
        const float4* q4 = (const float4*)qs[w];
        for (int j = lane; j <= own; j += 32) {
            const float4* kr = (const float4*)(g_ckf + (h*65 + j)*64);
            float acc = 0.f;
#pragma unroll
            for (int d4 = 0; d4 < 16; d4++) {
                float4 kv = kr[d4]; float4 qv = q4[d4];
                acc += qv.x*kv.x + qv.y*kv.y + qv.z*kv.z + qv.w*kv.w;
            }
            sc[w][j] = acc * SCALE;
        }
        __syncwarp();
        float m = -INFINITY;
        for (int j = lane; j <= own; j += 32) m = fmaxf(m, sc[w][j]);
#pragma unroll
        for (int o = 16; o > 0; o >>= 1) m = fmaxf(m, __shfl_xor_sync(0xFFFFFFFFu, m, o));
        float s = 0.f;
        for (int j = lane; j <= own; j += 32) { float e = __expf(sc[w][j] - m); sc[w][j] = e; s += e; }
#pragma unroll
        for (int o = 16; o > 0; o >>= 1) s += __shfl_xor_sync(0xFFFFFFFFu, s, o);
        float inv = 1.f / s;
        __syncwarp();
        float a0 = 0.f, a1 = 0.f;
#pragma unroll 4
        for (int j = 0; j <= own; j++) {
            float a = sc[w][j] * inv;
            const float* vr = g_cvf + (h*65 + j)*64;
            a0 += a * vr[lane]; a1 += a * vr[lane + 32];
        }
        g_cout[(h*NN + i)*64 + lane] = a0;
        g_cout[(h*NN + i)*64 + lane + 32] = a1;
        unsigned long long k0 = 0ULL, k1 = 0ULL;
        if (lane < own)
            k0 = ((unsigned long long)__float_as_uint(sc[w][1 + lane]) << 32)
               | (unsigned)(0xFFFFFFFFu - lane);
        if (lane + 32 < own)
            k1 = ((unsigned long long)__float_as_uint(sc[w][1 + lane + 32]) << 32)
               | (unsigned)(0xFFFFFFFFu - (lane + 32));
        int nv = 0;
#pragma unroll
        for (int t = 0; t < 8; t++) {
            unsigned long long mk = (k0 > k1) ? k0 : k1;
#pragma unroll
            for (int o = 16; o > 0; o >>= 1) {
                unsigned long long other = __shfl_xor_sync(0xFFFFFFFFu, mk, o);
                if (other > mk) mk = other;
            }
            if (mk) {
                int c = (int)(0xFFFFFFFFu - (unsigned)(mk & 0xFFFFFFFFu));
                if (k0 == mk) k0 = 0ULL;
                if (k1 == mk) k1 = 0ULL;
                if (lane == 0) selS[w][t] = c;
                nv = t + 1;
            } else if (lane == 0) selS[w][t] = 0;
        }
        __syncwarp();
        int nk = nv*16 + (i & 15) + 1;
        for (int kk = lane; kk < nk; kk += 32) {
            int tok = (kk < nv*16) ? selS[w][kk >> 4]*16 + (kk & 15) : own*16 + (kk - nv*16);
            const float4* kr = (const float4*)(g_k + (h*NN + tok)*64);
            float acc = 0.f;
#pragma unroll
            for (int d4 = 0; d4 < 16; d4++) {
                float4 kv = kr[d4]; float4 qv = q4[d4];
                acc += qv.x*kv.x + qv.y*kv.y + qv.z*kv.z + qv.w*kv.w;
            }
            sc[w][kk] = acc * SCALE;
        }
        __syncwarp();
        m = -INFINITY;
        for (int kk = lane; kk < nk; kk += 32) m = fmaxf(m, sc[w][kk]);
#pragma unroll
        for (int o = 16; o > 0; o >>= 1) m = fmaxf(m, __shfl_xor_sync(0xFFFFFFFFu, m, o));
        s = 0.f;
        for (int kk = lane; kk < nk; kk += 32) { float e = __expf(sc[w][kk] - m); sc[w][kk] = e; s += e; }
#pragma unroll
        for (int o = 16; o > 0; o >>= 1) s += __shfl_xor_sync(0xFFFFFFFFu, s, o);
        inv = 1.f / s;
        __syncwarp();
        a0 = 0.f; a1 = 0.f;
#pragma unroll 4
        for (int kk = 0; kk < nk; kk++) {
            int tok = (kk < nv*16) ? selS[w][kk >> 4]*16 + (kk & 15) : own*16 + (kk - nv*16);
            float a = sc[w][kk] * inv;
            const float* vr = g_v + (h*NN + tok)*64;
            a0 += a * vr[lane]; a1 += a * vr[lane + 32];
        }
        g_fout[(h*NN + i)*64 + lane] = a0;
        g_fout[(h*NN + i)*64 + lane + 32] = a1;
    } else {
        int qt = blockIdx.x - NN/8;
        int i0 = qt*16;
#pragma unroll
        for (int r = 0; r < 4; r++) {
            int idx = tid + r*256; int qi = idx >> 6, d = idx & 63;
            sqs[qi][d] = g_q[(h*NN + i0 + qi)*64 + d];
            saccs[qi][d] = 0.f;
        }
        if (tid < 16) { smrow[tid] = -INFINITY; slrow[tid] = 0.f; }
        __syncthreads();
        int t0 = (qt > 16) ? (qt - 16) : 0;
        for (int t = t0; t <= qt; t++) {
#pragma unroll
            for (int r = 0; r < 4; r++) {
                int idx = tid + r*256; int kj = idx >> 6, d = idx & 63;
                sks[kj][d] = g_k[(h*NN + t*16 + kj)*64 + d];
                svs[kj][d] = g_v[(h*NN + t*16 + kj)*64 + d];
            }
            __syncthreads();
            {
                int qi = tid >> 4, kj = tid & 15;
                int j = t*16 + kj, ii = i0 + qi;
                float s = 0.f;
#pragma unroll
                for (int d = 0; d < 64; d++) s += sqs[qi][d]*sks[kj][d];
                bool vis = (j <= ii) && (ii - j < 256);
                ssc[qi][kj] = vis ? s*SCALE : -INFINITY;
            }
            __syncthreads();
            if (tid < 16) {
                int qi = tid;
                float rm = -INFINITY;
                for (int kj = 0; kj < 16; kj++) rm = fmaxf(rm, ssc[qi][kj]);
                float nm = fmaxf(smrow[qi], rm);
                float al, rs = 0.f;
                if (nm == -INFINITY) {
                    al = 1.f;
                    for (int kj = 0; kj < 16; kj++) ssc[qi][kj] = 0.f;
                } else {
                    al = __expf(smrow[qi] - nm);
                    for (int kj = 0; kj < 16; kj++) {
                        float ee = __expf(ssc[qi][kj] - nm);
                        ssc[qi][kj] = ee; rs += ee;
                    }
                }
                smrow[qi] = nm; salpha[qi] = al; slrow[qi] = slrow[qi]*al + rs;
            }
            __syncthreads();
#pragma unroll
            for (int r = 0; r < 4; r++) {
                int idx = tid + r*256; int qi = idx >> 6, d = idx & 63;
                float a = saccs[qi][d]*salpha[qi];
#pragma unroll
                for (int kj = 0; kj < 16; kj++) a += ssc[qi][kj]*svs[kj][d];
                saccs[qi][d] = a;
            }
            __syncthreads();
        }
#pragma unroll
        for (int r = 0; r < 4; r++) {
            int idx = tid + r*256; int qi = idx >> 6, d = idx & 63;
            g_sout[(h*NN + i0 + qi)*64 + d] = saccs[qi][d] / slrow[qi];
        }
    }
}

// ---------------- gated combine -> bf16 hi/lo ----------------
__global__ void k_combine() {
    int n = blockIdx.x, c = threadIdx.x;
    int h = c >> 6, d = c & 63;
    const float* gl = g_gate + n*24 + h*3;
    float g0 = 1.f/(1.f + __expf(-gl[0]));
    float g1 = 1.f/(1.f + __expf(-gl[1]));
    float g2 = 1.f/(1.f + __expf(-gl[2]));
    int idx = (h*NN + n)*64 + d;
    float v = g0*g_cout[idx] + g1*g_fout[idx] + g2*g_sout[idx];
    __nv_bfloat16 hh, ll; split_bf(v, hh, ll);
    g_ohi[n*DIM + c] = hh; g_olo[n*DIM + c] = ll;
}

// ---------------- launch ----------------
extern "C" void kernel_launch(void* const* d_in, const int* in_sizes, int n_in,
                              void* d_out, int out_size) {
    const float* x    = (const float*)d_in[0];
    const float* x0   = (const float*)d_in[2];
    const float* lam  = (const float*)d_in[3];
    const float* Wq   = (const float*)d_in[4];
    const float* Wk   = (const float*)d_in[5];
    const float* Wv   = (const float*)d_in[6];
    const float* Wo   = (const float*)d_in[7];
    const float* Wg   = (const float*)d_in[8];
    const float* kpos = (const float*)d_in[9];
    const float* vpos = (const float*)d_in[10];
    const float* Wck  = (const float*)d_in[11];
    const float* bck  = (const float*)d_in[12];
    const float* Wcv  = (const float*)d_in[13];
    const float* bcv  = (const float*)d_in[14];
    const float* kmem = (const float*)d_in[15];
    const float* vmem = (const float*)d_in[16];
    const float* W1   = (const float*)d_in[17];
    const float* W2   = (const float*)d_in[18];
    float* out = (float*)d_out;

    float *p_xr, *p_x2;
    cudaGetSymbolAddress((void**)&p_xr,  g_xr);
    cudaGetSymbolAddress((void**)&p_x2,  g_x2);
    __nv_bfloat16 *p_xnh,*p_xnl,*p_ohi,*p_olo,*p_hhi,*p_hlo;
    __nv_bfloat16 *p_qkvTh,*p_qkvTl,*p_woTh,*p_woTl,*p_w1Th,*p_w1Tl,*p_w2Th,*p_w2Tl;
    cudaGetSymbolAddress((void**)&p_xnh, g_xnh);  cudaGetSymbolAddress((void**)&p_xnl, g_xnl);
    cudaGetSymbolAddress((void**)&p_ohi, g_ohi);  cudaGetSymbolAddress((void**)&p_olo, g_olo);
    cudaGetSymbolAddress((void**)&p_hhi, g_hhi);  cudaGetSymbolAddress((void**)&p_hlo, g_hlo);
    cudaGetSymbolAddress((void**)&p_qkvTh, g_wqkvTh); cudaGetSymbolAddress((void**)&p_qkvTl, g_wqkvTl);
    cudaGetSymbolAddress((void**)&p_woTh, g_woTh);   cudaGetSymbolAddress((void**)&p_woTl, g_woTl);
    cudaGetSymbolAddress((void**)&p_w1Th, g_w1Th);   cudaGetSymbolAddress((void**)&p_w1Tl, g_w1Tl);
    cudaGetSymbolAddress((void**)&p_w2Th, g_w2Th);   cudaGetSymbolAddress((void**)&p_w2Tl, g_w2Tl);

    const int SMB64 = 2*(32768 + 2*64*128);   // 98304
    const int SMB32 = 2*(32768 + 2*32*128);   // 81920
    cudaFuncSetAttribute(hm_gemm<64,3>, cudaFuncAttributeMaxDynamicSharedMemorySize, SMB64);
    cudaFuncSetAttribute(hm_gemm<64,2>, cudaFuncAttributeMaxDynamicSharedMemorySize, SMB64);
    cudaFuncSetAttribute(hm_gemm<32,1>, cudaFuncAttributeMaxDynamicSharedMemorySize, SMB32);

    k_convAll<<<3104, dim3(32,8)>>>(Wq, Wk, Wv, Wo, W1, W2, Wg);
    k_prelude<<<NN, 128>>>(x, x0, lam);

    // fused QKV+gates GEMM with rope/transpose epilogue: writes g_q/g_k/g_v/g_gate
    hm_gemm<64,3><<<dim3(25,8), 256, SMB64>>>(p_xnh, p_xnl, p_qkvTh, p_qkvTl,
                                              nullptr, nullptr, nullptr, nullptr, 512, 1600);

    k_ckcv<<<dim3(CC, 8), 512>>>(kpos, vpos, Wck, Wcv);
    k_ckred<<<CC, 512>>>(bck, bcv, kmem, vmem);

    // fused attention: 128 attn tiles + 64 sliding tiles per head
    k_attn_all<<<dim3(NN/8 + NN/16, HH), 256>>>();
    k_combine<<<NN, 512>>>();

    // x2 = xr + o @ Wo
    hm_gemm<32,1><<<dim3(16,8), 256, SMB32>>>(p_ohi, p_olo, p_woTh, p_woTl,
                                              p_xr, p_x2, nullptr, nullptr, 512, 512);
    k_rmsnorm2<<<NN, 128>>>();
    // h = relu(xn2 @ W1)^2 -> bf16 hi/lo
    hm_gemm<64,2><<<dim3(32,8), 256, SMB64>>>(p_xnh, p_xnl, p_w1Th, p_w1Tl,
                                              nullptr, nullptr, p_hhi, p_hlo, 512, 2048);
    // out = x2 + h @ W2
    hm_gemm<32,1><<<dim3(16,8), 256, SMB32>>>(p_hhi, p_hlo, p_w2Th, p_w2Tl,
                                              p_x2, out, nullptr, nullptr, 2048, 512);
}

// round 17
// speedup vs baseline: 1.6349x; 1.0085x over previous
#include <cuda_runtime.h>
#include <cuda_bf16.h>
#include <stdint.h>
#include <math.h>

#define NN 1024
#define DIM 512
#define HH 8
#define DD 64
#define CC 64
#define SCALE 0.125f
#define NEGF -1e30f

// ---------------- scratch ----------------
__device__ float g_xr [NN*DIM];
__device__ __nv_bfloat16 g_xnh[NN*DIM], g_xnl[NN*DIM];
__device__ float g_gate[NN*24];
__device__ float g_q  [HH*NN*DD];
__device__ float g_k  [HH*NN*DD];
__device__ float g_v  [HH*NN*DD];
__device__ float g_ckf[HH*65*DD];
__device__ float g_cvf[HH*65*DD];
__device__ float g_pck[HH*CC*8*DD];   // partial ck: [h][c][slice][d]
__device__ float g_pcv[HH*CC*8*DD];
__device__ float g_cout[HH*NN*DD];
__device__ float g_fout[HH*NN*DD];
__device__ float g_sout[HH*NN*DD];
__device__ __nv_bfloat16 g_ohi[NN*DIM], g_olo[NN*DIM];
__device__ float g_x2 [NN*DIM];
__device__ __nv_bfloat16 g_hhi[NN*2048], g_hlo[NN*2048];
// transposed bf16 hi/lo weights: [Nout][K]
__device__ __nv_bfloat16 g_wqkvTh[1600*512], g_wqkvTl[1600*512];
__device__ __nv_bfloat16 g_woTh[512*512],    g_woTl[512*512];
__device__ __nv_bfloat16 g_w1Th[2048*512],   g_w1Tl[2048*512];
__device__ __nv_bfloat16 g_w2Th[512*2048],   g_w2Tl[512*2048];

// ---------------- helpers ----------------
__device__ __forceinline__ uint32_t smem_u32(const void* p) {
    uint32_t a;
    asm("{ .reg .u64 t; cvta.to.shared.u64 t, %1; cvt.u32.u64 %0, t; }" : "=r"(a) : "l"(p));
    return a;
}
__device__ __forceinline__ uint32_t swz(uint32_t off) { return off ^ ((off >> 3) & 0x70); }

#define LDSM_X4(r, addr) \
    asm volatile("ldmatrix.sync.aligned.m8n8.x4.shared.b16 {%0,%1,%2,%3}, [%4];" \
        : "=r"((r)[0]),"=r"((r)[1]),"=r"((r)[2]),"=r"((r)[3]) : "r"(addr))
#define LDSM_X2(r, addr) \
    asm volatile("ldmatrix.sync.aligned.m8n8.x2.shared.b16 {%0,%1}, [%2];" \
        : "=r"((r)[0]),"=r"((r)[1]) : "r"(addr))
#define CP16(dst, src) \
    asm volatile("cp.async.cg.shared.global [%0], [%1], 16;" :: "r"(dst), "l"(src))
#define CP_COMMIT() asm volatile("cp.async.commit_group;" ::: "memory")
#define CP_WAIT(n)  asm volatile("cp.async.wait_group %0;" :: "n"(n) : "memory")

__device__ __forceinline__ void mma16816(float* d, const uint32_t* a, const uint32_t* b) {
    asm volatile("mma.sync.aligned.m16n8k16.row.col.f32.bf16.bf16.f32 "
        "{%0,%1,%2,%3}, {%4,%5,%6,%7}, {%8,%9}, {%0,%1,%2,%3};"
        : "+f"(d[0]),"+f"(d[1]),"+f"(d[2]),"+f"(d[3])
        : "r"(a[0]),"r"(a[1]),"r"(a[2]),"r"(a[3]), "r"(b[0]),"r"(b[1]));
}
__device__ __forceinline__ void split_bf(float x, __nv_bfloat16& h, __nv_bfloat16& l) {
    h = __float2bfloat16(x);
    l = __float2bfloat16(x - __bfloat162float(h));
}

// ---------------- fused weight transpose+split + prelude ----------------
// blocks [0,3104): weight tiles.  blocks [3104,4128): prelude rows.
__global__ void k_convAll(const float* __restrict__ Wq, const float* __restrict__ Wk,
                          const float* __restrict__ Wv, const float* __restrict__ Wo,
                          const float* __restrict__ W1, const float* __restrict__ W2,
                          const float* __restrict__ Wg,
                          const float* __restrict__ x, const float* __restrict__ x0,
                          const float* __restrict__ lam) {
    __shared__ __nv_bfloat16 th[32][33], tl[32][33];
    __shared__ float red[256];
    int t = blockIdx.x;
    int tid = threadIdx.y*32 + threadIdx.x;
    if (t >= 3104) {
        // ---- prelude: one row, 256 threads, 2 elems each ----
        int n = t - 3104;
        float l0 = lam[0], l1 = lam[1];
        float v[2]; float ss = 0.f;
#pragma unroll
        for (int r = 0; r < 2; r++) {
            int d = tid + r*256;
            float tt = l0*x[n*DIM+d] + l1*x0[n*DIM+d];
            v[r] = tt; g_xr[n*DIM+d] = tt; ss += tt*tt;
        }
        red[tid] = ss; __syncthreads();
        for (int s = 128; s > 0; s >>= 1) { if (tid < s) red[tid] += red[tid+s]; __syncthreads(); }
        float rms = rsqrtf(red[0]*(1.f/512.f) + 1e-6f);
#pragma unroll
        for (int r = 0; r < 2; r++) {
            int d = tid + r*256; float tt = v[r]*rms;
            __nv_bfloat16 h, l; split_bf(tt, h, l);
            g_xnh[n*DIM+d] = h; g_xnl[n*DIM+d] = l;
        }
        return;
    }
    const float* src; __nv_bfloat16 *dh, *dl;
    int K, N, rowOff; bool wg = false;
    if (t < 1024) {
        int s = t >> 8; t &= 255; K = 512; N = 512;
        if (s == 0)      { src = Wq; dh = g_wqkvTh; dl = g_wqkvTl; rowOff = 0; }
        else if (s == 1) { src = Wk; dh = g_wqkvTh; dl = g_wqkvTl; rowOff = 512; }
        else if (s == 2) { src = Wv; dh = g_wqkvTh; dl = g_wqkvTl; rowOff = 1024; }
        else             { src = Wo; dh = g_woTh;   dl = g_woTl;   rowOff = 0; }
    } else if (t < 2048) { t -= 1024; src = W1; dh = g_w1Th; dl = g_w1Tl; K = 512;  N = 2048; rowOff = 0; }
    else if (t < 3072)   { t -= 2048; src = W2; dh = g_w2Th; dl = g_w2Tl; K = 2048; N = 512;  rowOff = 0; }
    else { t -= 3072; src = Wg; dh = g_wqkvTh; dl = g_wqkvTl; K = 512; N = 64; rowOff = 1536; wg = true; }
    int tilesN = N >> 5;
    int tN = (t % tilesN)*32, tK = (t / tilesN)*32;
    int tx = threadIdx.x, ty = threadIdx.y;
#pragma unroll
    for (int r = 0; r < 4; r++) {
        int k = tK + ty + r*8, n = tN + tx;
        float v;
        if (wg) v = (n < 24) ? src[(size_t)k*24 + n] : 0.f;
        else    v = src[(size_t)k*N + n];
        __nv_bfloat16 h, l; split_bf(v, h, l);
        th[ty + r*8][tx] = h; tl[ty + r*8][tx] = l;
    }
    __syncthreads();
#pragma unroll
    for (int r = 0; r < 4; r++) {
        int n = tN + ty + r*8, k = tK + tx;
        size_t o = (size_t)(rowOff + n)*K + k;
        dh[o] = th[tx][ty + r*8];
        dl[o] = tl[tx][ty + r*8];
    }
}

// ---------------- HMMA GEMM with cp.async 2-stage pipeline ----------------
// MODE 1: Cf = acc + R.  MODE 2: Chi/Clo = split(relu(acc)^2).
// MODE 3 (QKV, TN=64): rope/transpose epilogue.
template<int TN, int MODE>
__global__ void __launch_bounds__(256, 2)
hm_gemm(const __nv_bfloat16* __restrict__ Ahi, const __nv_bfloat16* __restrict__ Alo,
        const __nv_bfloat16* __restrict__ Bhi, const __nv_bfloat16* __restrict__ Blo,
        const float* __restrict__ R, float* __restrict__ Cf,
        __nv_bfloat16* __restrict__ Chi, __nv_bfloat16* __restrict__ Clo,
        int K, int Nfull) {
    constexpr int NT = TN / 16;
    constexpr int STG = 32768 + 2*TN*128;
    extern __shared__ char dsm[];
    const uint32_t sb = smem_u32(dsm);
    int tid = threadIdx.x, wid = tid >> 5, lane = tid & 31;
    int wm = wid & 3, wn = wid >> 2;
    int rowBase = blockIdx.y*128, colBase = blockIdx.x*TN;

    float acc[2][NT][4];
#pragma unroll
    for (int mt = 0; mt < 2; mt++)
#pragma unroll
        for (int nt = 0; nt < NT; nt++)
#pragma unroll
            for (int r = 0; r < 4; r++) acc[mt][nt][r] = 0.f;

    auto issue = [&](int kc, int s) {
        uint32_t aH = sb + s*STG, aL = aH + 16384, bH = aH + 32768, bL = bH + TN*128;
        int rowL = tid >> 1, cb = (tid & 1)*4;
        const char* sAh = (const char*)(Ahi + ((size_t)(rowBase + rowL))*K + kc*64) + cb*16;
        const char* sAl = (const char*)(Alo + ((size_t)(rowBase + rowL))*K + kc*64) + cb*16;
#pragma unroll
        for (int j = 0; j < 4; j++) {
            uint32_t sw = swz((uint32_t)(rowL*128 + (cb + j)*16));
            CP16(aH + sw, sAh + j*16);
            CP16(aL + sw, sAl + j*16);
        }
#pragma unroll
        for (int it = 0; it < TN*8/256; it++) {
            int idx = tid + it*256;
            int n = idx >> 3, j = idx & 7;
            const char* sBh = (const char*)(Bhi + ((size_t)(colBase + n))*K + kc*64) + j*16;
            const char* sBl = (const char*)(Blo + ((size_t)(colBase + n))*K + kc*64) + j*16;
            uint32_t sw = swz((uint32_t)(n*128 + j*16));
            CP16(bH + sw, sBh);
            CP16(bL + sw, sBl);
        }
    };
    auto compute = [&](int s) {
        uint32_t A_H = sb + s*STG, A_L = A_H + 16384, B_H = A_H + 32768, B_L = B_H + TN*128;
#pragma unroll
        for (int ks = 0; ks < 4; ks++) {
            uint32_t ah[2][4], al[2][4], bh[NT][2], bl[NT][2];
#pragma unroll
            for (int mt = 0; mt < 2; mt++) {
                uint32_t off = swz((uint32_t)((wm*32 + mt*16 + (lane & 15))*128
                                              + ks*32 + (lane >> 4)*16));
                LDSM_X4(ah[mt], A_H + off);
                LDSM_X4(al[mt], A_L + off);
            }
#pragma unroll
            for (int nt = 0; nt < NT; nt++) {
                uint32_t off = swz((uint32_t)((wn*(TN/2) + nt*8 + (lane & 7))*128
                                              + ks*32 + ((lane >> 3) & 1)*16));
                LDSM_X2(bh[nt], B_H + off);
                LDSM_X2(bl[nt], B_L + off);
            }
#pragma unroll
            for (int mt = 0; mt < 2; mt++)
#pragma unroll
                for (int nt = 0; nt < NT; nt++) {
                    mma16816(acc[mt][nt], ah[mt], bh[nt]);
                    mma16816(acc[mt][nt], al[mt], bh[nt]);
                    mma16816(acc[mt][nt], ah[mt], bl[nt]);
                }
        }
    };

    int nCh = K >> 6;
    issue(0, 0); CP_COMMIT();
    for (int kc = 0; kc < nCh; kc++) {
        if (kc + 1 < nCh) { issue(kc + 1, (kc + 1) & 1); CP_COMMIT(); CP_WAIT(1); }
        else CP_WAIT(0);
        __syncthreads();
        compute(kc & 1);
        __syncthreads();
    }

    if (MODE == 3) {
        float* ts = (float*)dsm;   // [128][66]
#pragma unroll
        for (int mt = 0; mt < 2; mt++)
#pragma unroll
            for (int nt = 0; nt < NT; nt++)
#pragma unroll
                for (int half = 0; half < 2; half++) {
                    int rl = wm*32 + mt*16 + (lane >> 2) + half*8;
                    int cl = wn*(TN/2) + nt*8 + (lane & 3)*2;
                    ts[rl*66 + cl]     = acc[mt][nt][half*2];
                    ts[rl*66 + cl + 1] = acc[mt][nt][half*2 + 1];
                }
        __syncthreads();
        if (colBase >= 1536) {
            for (int idx = tid; idx < 128*24; idx += 256) {
                int r = idx / 24, c = idx - r*24;
                g_gate[(rowBase + r)*24 + c] = ts[r*66 + c];
            }
        } else {
            int h = (colBase >> 6) & 7;
            int kind = colBase >> 9;         // 0=q, 1=k, 2=v
            if (kind == 2) {
                for (int idx = tid; idx < 8192; idx += 256) {
                    int r = idx >> 6, d = idx & 63;
                    g_v[(h*NN + rowBase + r)*64 + d] = ts[r*66 + d];
                }
            } else {
                float* dst = kind ? g_k : g_q;
                for (int idx = tid; idx < 4096; idx += 256) {
                    int r = idx >> 5, dp = idx & 31;
                    int n = rowBase + r;
                    float inv = expf(-(float)dp * (9.210340371976184f/32.f));
                    float ang = (float)n * inv;
                    float cs = cosf(ang), sn = sinf(ang);
                    float a = ts[r*66 + dp], b = ts[r*66 + dp + 32];
                    int o = (h*NN + n)*64;
                    dst[o + dp]      = a*cs - b*sn;
                    dst[o + dp + 32] = b*cs + a*sn;
                }
            }
        }
        return;
    }

#pragma unroll
    for (int mt = 0; mt < 2; mt++) {
#pragma unroll
        for (int nt = 0; nt < NT; nt++) {
#pragma unroll
            for (int half = 0; half < 2; half++) {
                int r = rowBase + wm*32 + mt*16 + (lane >> 2) + half*8;
#pragma unroll
                for (int q = 0; q < 2; q++) {
                    int c = colBase + wn*(TN/2) + nt*8 + (lane & 3)*2 + q;
                    float v = acc[mt][nt][half*2 + q];
                    size_t o = (size_t)r*Nfull + c;
                    if (MODE == 2) {
                        v = fmaxf(v, 0.f); v *= v;
                        __nv_bfloat16 h, l; split_bf(v, h, l);
                        Chi[o] = h; Clo[o] = l;
                    } else {
                        if (MODE == 1) v += R[o];
                        Cf[o] = v;
                    }
                }
            }
        }
    }
}

__global__ void k_rmsnorm2() {
    int n = blockIdx.x, tid = threadIdx.x;
    __shared__ float red[128];
    float v[4]; float ss = 0.f;
#pragma unroll
    for (int r = 0; r < 4; r++) { int d = tid + r*128; float t = g_x2[n*DIM+d]; v[r]=t; ss += t*t; }
    red[tid] = ss; __syncthreads();
    for (int s = 64; s > 0; s >>= 1) { if (tid < s) red[tid] += red[tid+s]; __syncthreads(); }
    float rms = rsqrtf(red[0]*(1.f/512.f) + 1e-6f);
#pragma unroll
    for (int r = 0; r < 4; r++) {
        int d = tid + r*128; float t = v[r]*rms;
        __nv_bfloat16 h, l; split_bf(t, h, l);
        g_xnh[n*DIM+d] = h; g_xnl[n*DIM+d] = l;
    }
}

// ---------------- compressed K/V partial: grid (64 c, 8 slice), 512 thr, 2 CTA/SM ----------------
__global__ void __launch_bounds__(512, 2) k_ckcv(
        const float* __restrict__ kpos, const float* __restrict__ vpos,
        const float* __restrict__ Wck, const float* __restrict__ Wcv) {
    __shared__ float kbs[8][128], vbs[8][128];       // 8KB
    __shared__ float redk[8][8][64], redv[8][8][64]; // 32KB
    int c = blockIdx.x, s = blockIdx.y, tid = threadIdx.x;
    for (int idx = tid; idx < 1024; idx += 512) {
        int h = idx >> 7, el = idx & 127;
        int j = s*2 + (el >> 6), dd = el & 63;
        kbs[h][el] = g_k[(h*NN + c*16 + j)*64 + dd] + kpos[h*1024 + s*128 + el];
        vbs[h][el] = g_v[(h*NN + c*16 + j)*64 + dd] + vpos[h*1024 + s*128 + el];
    }
    __syncthreads();
    int part = tid >> 6, d = tid & 63;
    float ak[8] = {}, av[8] = {};
    int e0 = part*16;
#pragma unroll
    for (int e = 0; e < 16; e++) {
        float wk = Wck[(s*128 + e0 + e)*64 + d];
        float wv = Wcv[(s*128 + e0 + e)*64 + d];
#pragma unroll
        for (int h = 0; h < 8; h++) {
            ak[h] += kbs[h][e0 + e]*wk;
            av[h] += vbs[h][e0 + e]*wv;
        }
    }
#pragma unroll
    for (int h = 0; h < 8; h++) {
        redk[part][h][d] = ak[h];
        redv[part][h][d] = av[h];
    }
    __syncthreads();
    {
        int h = tid >> 6, dd = tid & 63;
        float sk = 0.f, sv = 0.f;
#pragma unroll
        for (int p = 0; p < 8; p++) {
            sk += redk[p][h][dd];
            sv += redv[p][h][dd];
        }
        size_t o = (size_t)(((h*CC + c)*8 + s))*64 + dd;
        g_pck[o] = sk; g_pcv[o] = sv;
    }
}

// reduce slices + bias + kmem/vmem: grid 64 c, 512 thr (h x d)
__global__ void __launch_bounds__(512) k_ckred(
        const float* __restrict__ bck, const float* __restrict__ bcv,
        const float* __restrict__ kmem, const float* __restrict__ vmem) {
    int c = blockIdx.x, tid = threadIdx.x;
    int h = tid >> 6, d = tid & 63;
    size_t base = (size_t)((h*CC + c)*8)*64 + d;
    float sk = bck[d], sv = bcv[d];
#pragma unroll
    for (int s = 0; s < 8; s++) {
        sk += g_pck[base + s*64];
        sv += g_pcv[base + s*64];
    }
    g_ckf[(h*65 + 1 + c)*64 + d] = sk;
    g_cvf[(h*65 + 1 + c)*64 + d] = sv;
    if (c == 0) {
        g_ckf[h*65*64 + d] = kmem[h*64 + d];
        g_cvf[h*65*64 + d] = vmem[h*64 + d];
    }
}

// ---------------- fused attention megakernel ----------------
__global__ void __launch_bounds__(256) k_attn_all() {
    __shared__ float qs[8][64];
    __shared__ float sc[8][160];
    __shared__ int selS[8][8];
    __shared__ float sqs[16][65], sks[16][65], svs[16][65], saccs[16][64], ssc[16][17];
    __shared__ float smrow[16], slrow[16], salpha[16];

    int h = blockIdx.y;
    int tid = threadIdx.x;

    if (blockIdx.x < NN/8) {
        int w = tid >> 5, lane = tid & 31;
        int i = blockIdx.x*8 + w;
        int own = i >> 4;
        const float* qp = g_q + (h*NN + i)*64;
        qs[w][lane] = qp[lane]; qs[w][lane + 32] = qp[lane + 32];
        __syncwarp();
        const float4* q4 = (const float4*)qs[w];
        for (int j = lane; j <= own; j += 32) {
            const float4* kr = (const float4*)(g_ckf + (h*65 + j)*64);
            float acc = 0.f;
#pragma unroll
            for (int d4 = 0; d4 < 16; d4++) {
                float4 kv = kr[d4]; float4 qv = q4[d4];
                acc += qv.x*kv.x + qv.y*kv.y + qv.z*kv.z + qv.w*kv.w;
            }
            sc[w][j] = acc * SCALE;
        }
        __syncwarp();
        float m = -INFINITY;
        for (int j = lane; j <= own; j += 32) m = fmaxf(m, sc[w][j]);
#pragma unroll
        for (int o = 16; o > 0; o >>= 1) m = fmaxf(m, __shfl_xor_sync(0xFFFFFFFFu, m, o));
        float s = 0.f;
        for (int j = lane; j <= own; j += 32) { float e = __expf(sc[w][j] - m); sc[w][j] = e; s += e; }
#pragma unroll
        for (int o = 16; o > 0; o >>= 1) s += __shfl_xor_sync(0xFFFFFFFFu, s, o);
        float inv = 1.f / s;
        __syncwarp();
        float a0 = 0.f, a1 = 0.f;
#pragma unroll 4
        for (int j = 0; j <= own; j++) {
            float a = sc[w][j] * inv;
            const float* vr = g_cvf + (h*65 + j)*64;
            a0 += a * vr[lane]; a1 += a * vr[lane + 32];
        }
        g_cout[(h*NN + i)*64 + lane] = a0;
        g_cout[(h*NN + i)*64 + lane + 32] = a1;
        unsigned long long k0 = 0ULL, k1 = 0ULL;
        if (lane < own)
            k0 = ((unsigned long long)__float_as_uint(sc[w][1 + lane]) << 32)
               | (unsigned)(0xFFFFFFFFu - lane);
        if (lane + 32 < own)
            k1 = ((unsigned long long)__float_as_uint(sc[w][1 + lane + 32]) << 32)
               | (unsigned)(0xFFFFFFFFu - (lane + 32));
        int nv = 0;
#pragma unroll
        for (int t = 0; t < 8; t++) {
            unsigned long long mk = (k0 > k1) ? k0 : k1;
#pragma unroll
            for (int o = 16; o > 0; o >>= 1) {
                unsigned long long other = __shfl_xor_sync(0xFFFFFFFFu, mk, o);
                if (other > mk) mk = other;
            }
            if (mk) {
                int c = (int)(0xFFFFFFFFu - (unsigned)(mk & 0xFFFFFFFFu));
                if (k0 == mk) k0 = 0ULL;
                if (k1 == mk) k1 = 0ULL;
                if (lane == 0) selS[w][t] = c;
                nv = t + 1;
            } else if (lane == 0) selS[w][t] = 0;
        }
        __syncwarp();
        int nk = nv*16 + (i & 15) + 1;
        for (int kk = lane; kk < nk; kk += 32) {
            int tok = (kk < nv*16) ? selS[w][kk >> 4]*16 + (kk & 15) : own*16 + (kk - nv*16);
            const float4* kr = (const float4*)(g_k + (h*NN + tok)*64);
            float acc = 0.f;
#pragma unroll
            for (int d4 = 0; d4 < 16; d4++) {
                float4 kv = kr[d4]; float4 qv = q4[d4];
                acc += qv.x*kv.x + qv.y*kv.y + qv.z*kv.z + qv.w*kv.w;
            }
            sc[w][kk] = acc * SCALE;
        }
        __syncwarp();
        m = -INFINITY;
        for (int kk = lane; kk < nk; kk += 32) m = fmaxf(m, sc[w][kk]);
#pragma unroll
        for (int o = 16; o > 0; o >>= 1) m = fmaxf(m, __shfl_xor_sync(0xFFFFFFFFu, m, o));
        s = 0.f;
        for (int kk = lane; kk < nk; kk += 32) { float e = __expf(sc[w][kk] - m); sc[w][kk] = e; s += e; }
#pragma unroll
        for (int o = 16; o > 0; o >>= 1) s += __shfl_xor_sync(0xFFFFFFFFu, s, o);
        inv = 1.f / s;
        __syncwarp();
        a0 = 0.f; a1 = 0.f;
#pragma unroll 4
        for (int kk = 0; kk < nk; kk++) {
            int tok = (kk < nv*16) ? selS[w][kk >> 4]*16 + (kk & 15) : own*16 + (kk - nv*16);
            float a = sc[w][kk] * inv;
            const float* vr = g_v + (h*NN + tok)*64;
            a0 += a * vr[lane]; a1 += a * vr[lane + 32];
        }
        g_fout[(h*NN + i)*64 + lane] = a0;
        g_fout[(h*NN + i)*64 + lane + 32] = a1;
    } else {
        int qt = blockIdx.x - NN/8;
        int i0 = qt*16;
#pragma unroll
        for (int r = 0; r < 4; r++) {
            int idx = tid + r*256; int qi = idx >> 6, d = idx & 63;
            sqs[qi][d] = g_q[(h*NN + i0 + qi)*64 + d];
            saccs[qi][d] = 0.f;
        }
        if (tid < 16) { smrow[tid] = -INFINITY; slrow[tid] = 0.f; }
        __syncthreads();
        int t0 = (qt > 16) ? (qt - 16) : 0;
        for (int t = t0; t <= qt; t++) {
#pragma unroll
            for (int r = 0; r < 4; r++) {
                int idx = tid + r*256; int kj = idx >> 6, d = idx & 63;
                sks[kj][d] = g_k[(h*NN + t*16 + kj)*64 + d];
                svs[kj][d] = g_v[(h*NN + t*16 + kj)*64 + d];
            }
            __syncthreads();
            {
                int qi = tid >> 4, kj = tid & 15;
                int j = t*16 + kj, ii = i0 + qi;
                float s = 0.f;
#pragma unroll
                for (int d = 0; d < 64; d++) s += sqs[qi][d]*sks[kj][d];
                bool vis = (j <= ii) && (ii - j < 256);
                ssc[qi][kj] = vis ? s*SCALE : -INFINITY;
            }
            __syncthreads();
            if (tid < 16) {
                int qi = tid;
                float rm = -INFINITY;
                for (int kj = 0; kj < 16; kj++) rm = fmaxf(rm, ssc[qi][kj]);
                float nm = fmaxf(smrow[qi], rm);
                float al, rs = 0.f;
                if (nm == -INFINITY) {
                    al = 1.f;
                    for (int kj = 0; kj < 16; kj++) ssc[qi][kj] = 0.f;
                } else {
                    al = __expf(smrow[qi] - nm);
                    for (int kj = 0; kj < 16; kj++) {
                        float ee = __expf(ssc[qi][kj] - nm);
                        ssc[qi][kj] = ee; rs += ee;
                    }
                }
                smrow[qi] = nm; salpha[qi] = al; slrow[qi] = slrow[qi]*al + rs;
            }
            __syncthreads();
#pragma unroll
            for (int r = 0; r < 4; r++) {
                int idx = tid + r*256; int qi = idx >> 6, d = idx & 63;
                float a = saccs[qi][d]*salpha[qi];
#pragma unroll
                for (int kj = 0; kj < 16; kj++) a += ssc[qi][kj]*svs[kj][d];
                saccs[qi][d] = a;
            }
            __syncthreads();
        }
#pragma unroll
        for (int r = 0; r < 4; r++) {
            int idx = tid + r*256; int qi = idx >> 6, d = idx & 63;
            g_sout[(h*NN + i0 + qi)*64 + d] = saccs[qi][d] / slrow[qi];
        }
    }
}

// ---------------- gated combine -> bf16 hi/lo ----------------
__global__ void k_combine() {
    int n = blockIdx.x, c = threadIdx.x;
    int h = c >> 6, d = c & 63;
    const float* gl = g_gate + n*24 + h*3;
    float g0 = 1.f/(1.f + __expf(-gl[0]));
    float g1 = 1.f/(1.f + __expf(-gl[1]));
    float g2 = 1.f/(1.f + __expf(-gl[2]));
    int idx = (h*NN + n)*64 + d;
    float v = g0*g_cout[idx] + g1*g_fout[idx] + g2*g_sout[idx];
    __nv_bfloat16 hh, ll; split_bf(v, hh, ll);
    g_ohi[n*DIM + c] = hh; g_olo[n*DIM + c] = ll;
}

// ---------------- launch ----------------
extern "C" void kernel_launch(void* const* d_in, const int* in_sizes, int n_in,
                              void* d_out, int out_size) {
    const float* x    = (const float*)d_in[0];
    const float* x0   = (const float*)d_in[2];
    const float* lam  = (const float*)d_in[3];
    const float* Wq   = (const float*)d_in[4];
    const float* Wk   = (const float*)d_in[5];
    const float* Wv   = (const float*)d_in[6];
    const float* Wo   = (const float*)d_in[7];
    const float* Wg   = (const float*)d_in[8];
    const float* kpos = (const float*)d_in[9];
    const float* vpos = (const float*)d_in[10];
    const float* Wck  = (const float*)d_in[11];
    const float* bck  = (const float*)d_in[12];
    const float* Wcv  = (const float*)d_in[13];
    const float* bcv  = (const float*)d_in[14];
    const float* kmem = (const float*)d_in[15];
    const float* vmem = (const float*)d_in[16];
    const float* W1   = (const float*)d_in[17];
    const float* W2   = (const float*)d_in[18];
    float* out = (float*)d_out;

    float *p_xr, *p_x2;
    cudaGetSymbolAddress((void**)&p_xr,  g_xr);
    cudaGetSymbolAddress((void**)&p_x2,  g_x2);
    __nv_bfloat16 *p_xnh,*p_xnl,*p_ohi,*p_olo,*p_hhi,*p_hlo;
    __nv_bfloat16 *p_qkvTh,*p_qkvTl,*p_woTh,*p_woTl,*p_w1Th,*p_w1Tl,*p_w2Th,*p_w2Tl;
    cudaGetSymbolAddress((void**)&p_xnh, g_xnh);  cudaGetSymbolAddress((void**)&p_xnl, g_xnl);
    cudaGetSymbolAddress((void**)&p_ohi, g_ohi);  cudaGetSymbolAddress((void**)&p_olo, g_olo);
    cudaGetSymbolAddress((void**)&p_hhi, g_hhi);  cudaGetSymbolAddress((void**)&p_hlo, g_hlo);
    cudaGetSymbolAddress((void**)&p_qkvTh, g_wqkvTh); cudaGetSymbolAddress((void**)&p_qkvTl, g_wqkvTl);
    cudaGetSymbolAddress((void**)&p_woTh, g_woTh);   cudaGetSymbolAddress((void**)&p_woTl, g_woTl);
    cudaGetSymbolAddress((void**)&p_w1Th, g_w1Th);   cudaGetSymbolAddress((void**)&p_w1Tl, g_w1Tl);
    cudaGetSymbolAddress((void**)&p_w2Th, g_w2Th);   cudaGetSymbolAddress((void**)&p_w2Tl, g_w2Tl);

    const int SMB64 = 2*(32768 + 2*64*128);   // 98304
    const int SMB32 = 2*(32768 + 2*32*128);   // 81920
    cudaFuncSetAttribute(hm_gemm<64,3>, cudaFuncAttributeMaxDynamicSharedMemorySize, SMB64);
    cudaFuncSetAttribute(hm_gemm<64,2>, cudaFuncAttributeMaxDynamicSharedMemorySize, SMB64);
    cudaFuncSetAttribute(hm_gemm<32,1>, cudaFuncAttributeMaxDynamicSharedMemorySize, SMB32);

    // weight converts + prelude fused (independent work, one launch)
    k_convAll<<<3104 + NN, dim3(32,8)>>>(Wq, Wk, Wv, Wo, W1, W2, Wg, x, x0, lam);

    // fused QKV+gates GEMM with rope/transpose epilogue: writes g_q/g_k/g_v/g_gate
    hm_gemm<64,3><<<dim3(25,8), 256, SMB64>>>(p_xnh, p_xnl, p_qkvTh, p_qkvTl,
                                              nullptr, nullptr, nullptr, nullptr, 512, 1600);

    k_ckcv<<<dim3(CC, 8), 512>>>(kpos, vpos, Wck, Wcv);
    k_ckred<<<CC, 512>>>(bck, bcv, kmem, vmem);

    // fused attention: 128 attn tiles + 64 sliding tiles per head
    k_attn_all<<<dim3(NN/8 + NN/16, HH), 256>>>();
    k_combine<<<NN, 512>>>();

    // x2 = xr + o @ Wo
    hm_gemm<32,1><<<dim3(16,8), 256, SMB32>>>(p_ohi, p_olo, p_woTh, p_woTl,
                                              p_xr, p_x2, nullptr, nullptr, 512, 512);
    k_rmsnorm2<<<NN, 128>>>();
    // h = relu(xn2 @ W1)^2 -> bf16 hi/lo
    hm_gemm<64,2><<<dim3(32,8), 256, SMB64>>>(p_xnh, p_xnl, p_w1Th, p_w1Tl,
                                              nullptr, nullptr, p_hhi, p_hlo, 512, 2048);
    // out = x2 + h @ W2
    hm_gemm<32,1><<<dim3(16,8), 256, SMB32>>>(p_hhi, p_hlo, p_w2Th, p_w2Tl,
                                              p_x2, out, nullptr, nullptr, 2048, 512);
}